// round 15
// baseline (speedup 1.0000x reference)
#include <cuda_runtime.h>
#include <cuda_fp16.h>
#include <math.h>

#define NMAX 50000
#define EMAX 800000
#define ETMAX (EMAX + NMAX)

// ---------------- scratch (device globals) -----------------------------------
__device__ __half g_h1h[NMAX * 256];
__device__ float g_asrc1[NMAX * 8];
__device__ float g_adst1[NMAX * 8];
__device__ __half g_out1h[NMAX * 256];
__device__ __half g_h2h[NMAX * 16];
__device__ float g_asrc2[NMAX];
__device__ float g_adst2[NMAX];
__device__ __half g_gh[NMAX * 16];
__device__ int   g_degi[NMAX];
__device__ int   g_rowptr[NMAX + 1];
__device__ int   g_esrc[ETMAX];
__device__ __half g_xh[NMAX * 128];
__device__ __half g_xl[NMAX * 128];
__device__ __half g_wth[256 * 128];
__device__ __half g_wtl[256 * 128];

__device__ __forceinline__ float lrelu(float x) { return x > 0.f ? x : 0.2f * x; }
__device__ __forceinline__ float eluf(float x) { return x > 0.f ? x : expm1f(x); }

// ---------------- CSR build ---------------------------------------------------
__global__ void k_deg(const int* __restrict__ ei, int E, int N, int* __restrict__ degi) {
    int e = blockIdx.x * blockDim.x + threadIdx.x;
    int ET = E + N;
    if (e >= ET) return;
    int d = (e < E) ? ei[E + e] : e - E;
    atomicAdd(&degi[d], 1);
}

// coalesced tiled exclusive scan (single block, 1024 threads)
__global__ void k_scan(const int* __restrict__ degi, int* __restrict__ rowptr,
                       int N, int ET) {
    __shared__ int warpsum[32];
    __shared__ int carry;
    int t = threadIdx.x;
    int lane = t & 31, wid = t >> 5;
    if (t == 0) carry = 0;
    __syncthreads();
    for (int base = 0; base < N; base += 1024) {
        int i = base + t;
        int v = (i < N) ? degi[i] : 0;
        int s = v;
#pragma unroll
        for (int off = 1; off < 32; off <<= 1) {
            int u = __shfl_up_sync(0xffffffffu, s, off);
            if (lane >= off) s += u;
        }
        if (lane == 31) warpsum[wid] = s;
        __syncthreads();
        if (wid == 0) {
            int ws = warpsum[lane];
#pragma unroll
            for (int off = 1; off < 32; off <<= 1) {
                int u = __shfl_up_sync(0xffffffffu, ws, off);
                if (lane >= off) ws += u;
            }
            warpsum[lane] = ws;
        }
        __syncthreads();
        int woff = (wid == 0) ? 0 : warpsum[wid - 1];
        int excl = carry + woff + s - v;
        if (i < N) rowptr[i] = excl;
        __syncthreads();
        if (t == 0) carry += warpsum[31];
        __syncthreads();
    }
    if (t == 0) rowptr[N] = ET;
}

// fill: 2 edges per thread; slot allocation via atomicSub on degi (no cursor).
// After this kernel degi is all zeros again (exactly consumed).
__global__ void k_fill(const int* __restrict__ ei, int E, int N,
                       const int* __restrict__ rowptr, int* __restrict__ degi,
                       int* __restrict__ esrc) {
    int i = blockIdx.x * blockDim.x + threadIdx.x;
    int ET = E + N;
    int e0 = 2 * i, e1 = 2 * i + 1;
    if (e0 >= ET) return;
    int s0, d0;
    if (e0 < E) { s0 = ei[e0]; d0 = ei[E + e0]; } else { s0 = d0 = e0 - E; }
    if (e1 < ET) {
        int s1, d1;
        if (e1 < E) { s1 = ei[e1]; d1 = ei[E + e1]; } else { s1 = d1 = e1 - E; }
        int p0 = rowptr[d0] + atomicSub(&degi[d0], 1) - 1;
        int p1 = rowptr[d1] + atomicSub(&degi[d1], 1) - 1;
        esrc[p0] = s0;
        esrc[p1] = s1;
    } else {
        int p0 = rowptr[d0] + atomicSub(&degi[d0], 1) - 1;
        esrc[p0] = s0;
    }
}

// ---------------- helpers ------------------------------------------------------
__device__ __forceinline__ void mma_f16(float* d, const unsigned* a, const unsigned* b) {
    asm volatile("mma.sync.aligned.m16n8k16.row.col.f32.f16.f16.f32 "
                 "{%0,%1,%2,%3}, {%4,%5,%6,%7}, {%8,%9}, {%0,%1,%2,%3};"
                 : "+f"(d[0]), "+f"(d[1]), "+f"(d[2]), "+f"(d[3])
                 : "r"(a[0]), "r"(a[1]), "r"(a[2]), "r"(a[3]),
                   "r"(b[0]), "r"(b[1]));
}

__device__ __forceinline__ void cpasync16(void* dst, const void* src) {
    unsigned d = (unsigned)__cvta_generic_to_shared(dst);
    asm volatile("cp.async.cg.shared.global [%0], [%1], 16;" :: "r"(d), "l"(src));
}

__device__ __forceinline__ void f16split(float x, __half& hi, __half& lo) {
    hi = __float2half_rn(x);
    lo = __float2half_rn(x - __half2float(hi));
}

// ---------------- split X: f32 -> hi/lo fp16 planes ---------------------------
__global__ void k_splitX(const float* __restrict__ src, __half* __restrict__ dh,
                         __half* __restrict__ dl, int total8) {
    int i = blockIdx.x * blockDim.x + threadIdx.x;
    if (i >= total8) return;
    const float4* s4 = reinterpret_cast<const float4*>(src) + (size_t)i * 2;
    float4 v0 = s4[0], v1 = s4[1];
    __half h[8], l[8];
    f16split(v0.x, h[0], l[0]); f16split(v0.y, h[1], l[1]);
    f16split(v0.z, h[2], l[2]); f16split(v0.w, h[3], l[3]);
    f16split(v1.x, h[4], l[4]); f16split(v1.y, h[5], l[5]);
    f16split(v1.z, h[6], l[6]); f16split(v1.w, h[7], l[7]);
    *reinterpret_cast<uint4*>(dh + (size_t)i * 8) = *reinterpret_cast<uint4*>(h);
    *reinterpret_cast<uint4*>(dl + (size_t)i * 8) = *reinterpret_cast<uint4*>(l);
}

// ---------------- split + transpose W1 ----------------------------------------
__global__ void k_splitW(const float* __restrict__ W1, __half* __restrict__ dh,
                         __half* __restrict__ dl) {
    int i = blockIdx.x * blockDim.x + threadIdx.x;
    if (i >= 256 * 16) return;
    int n = i >> 4, kq = i & 15;
    __half h[8], l[8];
#pragma unroll
    for (int j = 0; j < 8; j++)
        f16split(W1[(kq * 8 + j) * 256 + n], h[j], l[j]);
    *reinterpret_cast<uint4*>(dh + (size_t)n * 128 + kq * 8) = *reinterpret_cast<uint4*>(h);
    *reinterpret_cast<uint4*>(dl + (size_t)n * 128 + kq * 8) = *reinterpret_cast<uint4*>(l);
}

// ---------------- GEMM1 (fp16 2-term split, m16n8k16, fused alpha) ------------
#define ASTR 24
#define PL   (128 * ASTR)
#define STG  (4 * PL)
#define SMEM_H (2 * STG)

__global__ __launch_bounds__(256) void k_gemm1_tc3(
        const __half* __restrict__ xh, const __half* __restrict__ xl,
        const __half* __restrict__ wth, const __half* __restrict__ wtl,
        const float* __restrict__ a_src, const float* __restrict__ a_dst,
        __half* __restrict__ h1h, float* __restrict__ asrcn, float* __restrict__ adstn,
        int N) {
    extern __shared__ __half smh[];
    const int t = threadIdx.x;
    const int warp = t >> 5, lane = t & 31;
    const int wm = warp >> 2, wn = warp & 3;
    const int lm = lane >> 2, lk = lane & 3;
    const int r0 = blockIdx.x * 128;
    const int n0 = blockIdx.y * 128;

    float acc[4][4][4];
#pragma unroll
    for (int i = 0; i < 4; i++)
#pragma unroll
        for (int j = 0; j < 4; j++)
#pragma unroll
            for (int v = 0; v < 4; v++) acc[i][j][v] = 0.f;

    auto issue = [&](int c, int buf) {
        int k0 = c * 16;
        __half* base = smh + buf * STG;
        int row = t >> 1, seg = t & 1;
        int gr = r0 + row; if (gr > N - 1) gr = N - 1;
        cpasync16(base + row * ASTR + seg * 8,
                  xh + (size_t)gr * 128 + k0 + seg * 8);
        cpasync16(base + PL + row * ASTR + seg * 8,
                  xl + (size_t)gr * 128 + k0 + seg * 8);
        cpasync16(base + 2 * PL + row * ASTR + seg * 8,
                  wth + (size_t)(n0 + row) * 128 + k0 + seg * 8);
        cpasync16(base + 3 * PL + row * ASTR + seg * 8,
                  wtl + (size_t)(n0 + row) * 128 + k0 + seg * 8);
        asm volatile("cp.async.commit_group;");
    };

    issue(0, 0);
    for (int c = 0; c < 8; c++) {
        int buf = c & 1;
        if (c < 7) {
            issue(c + 1, buf ^ 1);
            asm volatile("cp.async.wait_group 1;");
        } else {
            asm volatile("cp.async.wait_group 0;");
        }
        __syncthreads();
        const __half* Ah = smh + buf * STG;
        const __half* Al = Ah + PL;
        const __half* Bh = Ah + 2 * PL;
        const __half* Bl = Ah + 3 * PL;
        const int kb = lk * 2;

        unsigned Ahf[4][4], Alf[4][4];
#pragma unroll
        for (int mt = 0; mt < 4; mt++) {
            int mrow = wm * 64 + mt * 16 + lm;
            Ahf[mt][0] = *reinterpret_cast<const unsigned*>(Ah + mrow * ASTR + kb);
            Ahf[mt][1] = *reinterpret_cast<const unsigned*>(Ah + (mrow + 8) * ASTR + kb);
            Ahf[mt][2] = *reinterpret_cast<const unsigned*>(Ah + mrow * ASTR + kb + 8);
            Ahf[mt][3] = *reinterpret_cast<const unsigned*>(Ah + (mrow + 8) * ASTR + kb + 8);
            Alf[mt][0] = *reinterpret_cast<const unsigned*>(Al + mrow * ASTR + kb);
            Alf[mt][1] = *reinterpret_cast<const unsigned*>(Al + (mrow + 8) * ASTR + kb);
            Alf[mt][2] = *reinterpret_cast<const unsigned*>(Al + mrow * ASTR + kb + 8);
            Alf[mt][3] = *reinterpret_cast<const unsigned*>(Al + (mrow + 8) * ASTR + kb + 8);
        }
        unsigned Bhf[4][2], Blf[4][2];
#pragma unroll
        for (int nt = 0; nt < 4; nt++) {
            int n = wn * 32 + nt * 8 + lm;
            Bhf[nt][0] = *reinterpret_cast<const unsigned*>(Bh + n * ASTR + kb);
            Bhf[nt][1] = *reinterpret_cast<const unsigned*>(Bh + n * ASTR + kb + 8);
            Blf[nt][0] = *reinterpret_cast<const unsigned*>(Bl + n * ASTR + kb);
            Blf[nt][1] = *reinterpret_cast<const unsigned*>(Bl + n * ASTR + kb + 8);
        }
#pragma unroll
        for (int mt = 0; mt < 4; mt++)
#pragma unroll
            for (int nt = 0; nt < 4; nt++) {
                mma_f16(acc[mt][nt], Ahf[mt], Bhf[nt]);
                mma_f16(acc[mt][nt], Ahf[mt], Blf[nt]);
                mma_f16(acc[mt][nt], Alf[mt], Bhf[nt]);
            }
        __syncthreads();
    }

    const int h = blockIdx.y * 4 + wn;
    float2 asv[4], adv[4];
#pragma unroll
    for (int nt = 0; nt < 4; nt++) {
        asv[nt] = *reinterpret_cast<const float2*>(a_src + h * 32 + nt * 8 + lk * 2);
        adv[nt] = *reinterpret_cast<const float2*>(a_dst + h * 32 + nt * 8 + lk * 2);
    }
#pragma unroll
    for (int mt = 0; mt < 4; mt++) {
        int row1 = r0 + wm * 64 + mt * 16 + lm;
        int row2 = row1 + 8;
        float s1 = 0.f, d1 = 0.f, s2 = 0.f, d2 = 0.f;
#pragma unroll
        for (int nt = 0; nt < 4; nt++) {
            int col = n0 + wn * 32 + nt * 8 + lk * 2;
            s1 += acc[mt][nt][0] * asv[nt].x + acc[mt][nt][1] * asv[nt].y;
            d1 += acc[mt][nt][0] * adv[nt].x + acc[mt][nt][1] * adv[nt].y;
            s2 += acc[mt][nt][2] * asv[nt].x + acc[mt][nt][3] * asv[nt].y;
            d2 += acc[mt][nt][2] * adv[nt].x + acc[mt][nt][3] * adv[nt].y;
            if (row1 < N)
                *reinterpret_cast<__half2*>(h1h + (size_t)row1 * 256 + col) =
                    __floats2half2_rn(acc[mt][nt][0], acc[mt][nt][1]);
            if (row2 < N)
                *reinterpret_cast<__half2*>(h1h + (size_t)row2 * 256 + col) =
                    __floats2half2_rn(acc[mt][nt][2], acc[mt][nt][3]);
        }
        s1 += __shfl_xor_sync(0xffffffffu, s1, 1); s1 += __shfl_xor_sync(0xffffffffu, s1, 2);
        d1 += __shfl_xor_sync(0xffffffffu, d1, 1); d1 += __shfl_xor_sync(0xffffffffu, d1, 2);
        s2 += __shfl_xor_sync(0xffffffffu, s2, 1); s2 += __shfl_xor_sync(0xffffffffu, s2, 2);
        d2 += __shfl_xor_sync(0xffffffffu, d2, 1); d2 += __shfl_xor_sync(0xffffffffu, d2, 2);
        if (lk == 0) {
            if (row1 < N) { asrcn[row1 * 8 + h] = s1; adstn[row1 * 8 + h] = d1; }
            if (row2 < N) { asrcn[row2 * 8 + h] = s2; adstn[row2 * 8 + h] = d2; }
        }
    }
}

// ----- GAT1 pull aggregation: warp per dst, per-lane head weights, unroll x4 --
__global__ void k_agg1(const int* __restrict__ rowptr, const int* __restrict__ esrc,
                       const float* __restrict__ asrc, const float* __restrict__ adst,
                       const __half* __restrict__ h1h, const float* __restrict__ b1,
                       __half* __restrict__ out1h, int N) {
    int d = (int)(((long long)blockIdx.x * blockDim.x + threadIdx.x) >> 5);
    int lane = threadIdx.x & 31;
    if (d >= N) return;
    int beg = rowptr[d], endp = rowptr[d + 1];
    const int h0 = lane >> 2;
    float ad = adst[d * 8 + h0];
    float den = 0.f;
    float accv[8];
#pragma unroll
    for (int i = 0; i < 8; i++) accv[i] = 0.f;
    for (int base = beg; base < endp; base += 32) {
        int nn = min(32, endp - base);
        int sreg = (base + lane < endp) ? esrc[base + lane] : 0;
        int j = 0;
        for (; j + 3 < nn; j += 4) {
            int s0 = __shfl_sync(0xffffffffu, sreg, j);
            int s1 = __shfl_sync(0xffffffffu, sreg, j + 1);
            int s2 = __shfl_sync(0xffffffffu, sreg, j + 2);
            int s3 = __shfl_sync(0xffffffffu, sreg, j + 3);
            float w0 = __expf(lrelu(asrc[s0 * 8 + h0] + ad));
            float w1 = __expf(lrelu(asrc[s1 * 8 + h0] + ad));
            float w2 = __expf(lrelu(asrc[s2 * 8 + h0] + ad));
            float w3 = __expf(lrelu(asrc[s3 * 8 + h0] + ad));
            den += (w0 + w1) + (w2 + w3);
            uint4 r0 = *reinterpret_cast<const uint4*>(h1h + (size_t)s0 * 256 + lane * 8);
            uint4 r1 = *reinterpret_cast<const uint4*>(h1h + (size_t)s1 * 256 + lane * 8);
            uint4 r2 = *reinterpret_cast<const uint4*>(h1h + (size_t)s2 * 256 + lane * 8);
            uint4 r3 = *reinterpret_cast<const uint4*>(h1h + (size_t)s3 * 256 + lane * 8);
            {
                float2 f0 = __half22float2(*reinterpret_cast<__half2*>(&r0.x));
                float2 f1 = __half22float2(*reinterpret_cast<__half2*>(&r0.y));
                float2 f2 = __half22float2(*reinterpret_cast<__half2*>(&r0.z));
                float2 f3 = __half22float2(*reinterpret_cast<__half2*>(&r0.w));
                accv[0] += f0.x * w0; accv[1] += f0.y * w0;
                accv[2] += f1.x * w0; accv[3] += f1.y * w0;
                accv[4] += f2.x * w0; accv[5] += f2.y * w0;
                accv[6] += f3.x * w0; accv[7] += f3.y * w0;
            }
            {
                float2 f0 = __half22float2(*reinterpret_cast<__half2*>(&r1.x));
                float2 f1 = __half22float2(*reinterpret_cast<__half2*>(&r1.y));
                float2 f2 = __half22float2(*reinterpret_cast<__half2*>(&r1.z));
                float2 f3 = __half22float2(*reinterpret_cast<__half2*>(&r1.w));
                accv[0] += f0.x * w1; accv[1] += f0.y * w1;
                accv[2] += f1.x * w1; accv[3] += f1.y * w1;
                accv[4] += f2.x * w1; accv[5] += f2.y * w1;
                accv[6] += f3.x * w1; accv[7] += f3.y * w1;
            }
            {
                float2 f0 = __half22float2(*reinterpret_cast<__half2*>(&r2.x));
                float2 f1 = __half22float2(*reinterpret_cast<__half2*>(&r2.y));
                float2 f2 = __half22float2(*reinterpret_cast<__half2*>(&r2.z));
                float2 f3 = __half22float2(*reinterpret_cast<__half2*>(&r2.w));
                accv[0] += f0.x * w2; accv[1] += f0.y * w2;
                accv[2] += f1.x * w2; accv[3] += f1.y * w2;
                accv[4] += f2.x * w2; accv[5] += f2.y * w2;
                accv[6] += f3.x * w2; accv[7] += f3.y * w2;
            }
            {
                float2 f0 = __half22float2(*reinterpret_cast<__half2*>(&r3.x));
                float2 f1 = __half22float2(*reinterpret_cast<__half2*>(&r3.y));
                float2 f2 = __half22float2(*reinterpret_cast<__half2*>(&r3.z));
                float2 f3 = __half22float2(*reinterpret_cast<__half2*>(&r3.w));
                accv[0] += f0.x * w3; accv[1] += f0.y * w3;
                accv[2] += f1.x * w3; accv[3] += f1.y * w3;
                accv[4] += f2.x * w3; accv[5] += f2.y * w3;
                accv[6] += f3.x * w3; accv[7] += f3.y * w3;
            }
        }
        for (; j < nn; j++) {
            int s = __shfl_sync(0xffffffffu, sreg, j);
            float a = __expf(lrelu(asrc[s * 8 + h0] + ad));
            den += a;
            uint4 r = *reinterpret_cast<const uint4*>(h1h + (size_t)s * 256 + lane * 8);
            float2 f0 = __half22float2(*reinterpret_cast<__half2*>(&r.x));
            float2 f1 = __half22float2(*reinterpret_cast<__half2*>(&r.y));
            float2 f2 = __half22float2(*reinterpret_cast<__half2*>(&r.z));
            float2 f3 = __half22float2(*reinterpret_cast<__half2*>(&r.w));
            accv[0] += f0.x * a; accv[1] += f0.y * a;
            accv[2] += f1.x * a; accv[3] += f1.y * a;
            accv[4] += f2.x * a; accv[5] += f2.y * a;
            accv[6] += f3.x * a; accv[7] += f3.y * a;
        }
    }
    float rs = 1.f / den;
    const float4* bp = reinterpret_cast<const float4*>(b1 + lane * 8);
    float4 bb0 = bp[0], bb1 = bp[1];
    float o[8];
    o[0] = eluf(accv[0] * rs + bb0.x); o[1] = eluf(accv[1] * rs + bb0.y);
    o[2] = eluf(accv[2] * rs + bb0.z); o[3] = eluf(accv[3] * rs + bb0.w);
    o[4] = eluf(accv[4] * rs + bb1.x); o[5] = eluf(accv[5] * rs + bb1.y);
    o[6] = eluf(accv[6] * rs + bb1.z); o[7] = eluf(accv[7] * rs + bb1.w);
    __half2 p0 = __floats2half2_rn(o[0], o[1]);
    __half2 p1 = __floats2half2_rn(o[2], o[3]);
    __half2 p2 = __floats2half2_rn(o[4], o[5]);
    __half2 p3 = __floats2half2_rn(o[6], o[7]);
    uint4 pk;
    pk.x = *reinterpret_cast<unsigned*>(&p0);
    pk.y = *reinterpret_cast<unsigned*>(&p1);
    pk.z = *reinterpret_cast<unsigned*>(&p2);
    pk.w = *reinterpret_cast<unsigned*>(&p3);
    *reinterpret_cast<uint4*>(out1h + (size_t)d * 256 + lane * 8) = pk;
}

// ----- GEMM2: h2 = x2[N,256] @ W2[256,16], fp16 in (uint4), fused alpha2 -----
__global__ void k_gemm2(const __half* __restrict__ x2h, const float* __restrict__ W2,
                        const float* __restrict__ a_src2, const float* __restrict__ a_dst2,
                        __half* __restrict__ h2h, float* __restrict__ asrc2n,
                        float* __restrict__ adst2n, int N) {
    __shared__ float Wsh[256 * 16];
    int t = threadIdx.x;
    for (int i = t; i < 4096; i += 256) Wsh[i] = W2[i];
    __syncthreads();
    int n = blockIdx.x * 16 + (t >> 4);
    int c = t & 15;
    if (n >= N) return;
    float acc = 0.f;
    const uint4* xr4 = reinterpret_cast<const uint4*>(x2h + (size_t)n * 256);
#pragma unroll 8
    for (int kq = 0; kq < 32; kq++) {
        uint4 r = xr4[kq];
        float2 f0 = __half22float2(*reinterpret_cast<__half2*>(&r.x));
        float2 f1 = __half22float2(*reinterpret_cast<__half2*>(&r.y));
        float2 f2 = __half22float2(*reinterpret_cast<__half2*>(&r.z));
        float2 f3 = __half22float2(*reinterpret_cast<__half2*>(&r.w));
        const float* wb = Wsh + (kq * 8) * 16 + c;
        acc += f0.x * wb[0]   + f0.y * wb[16]
             + f1.x * wb[32]  + f1.y * wb[48]
             + f2.x * wb[64]  + f2.y * wb[80]
             + f3.x * wb[96]  + f3.y * wb[112];
    }
    h2h[(size_t)n * 16 + c] = __float2half(acc);
    float r1 = acc * a_src2[c];
    float r2 = acc * a_dst2[c];
#pragma unroll
    for (int m = 8; m >= 1; m >>= 1) {
        r1 += __shfl_xor_sync(0xffffffffu, r1, m, 16);
        r2 += __shfl_xor_sync(0xffffffffu, r2, m, 16);
    }
    if (c == 0) { asrc2n[n] = r1; adst2n[n] = r2; }
}

// ----- GAT2 pull aggregation + fused GCN transform (h3), unroll x4 -----------
__global__ void k_agg2(const int* __restrict__ rowptr, const int* __restrict__ esrc,
                       const float* __restrict__ asrc, const float* __restrict__ adst,
                       const __half* __restrict__ h2h, const float* __restrict__ b2,
                       const float* __restrict__ W3, __half* __restrict__ gh, int N) {
    __shared__ float W3s[256];
    if (threadIdx.x < 256) W3s[threadIdx.x] = W3[threadIdx.x];
    __syncthreads();
    long long gt = (long long)blockIdx.x * blockDim.x + threadIdx.x;
    int d = (int)(gt >> 2);
    int q = threadIdx.x & 3;
    if (d >= N) return;
    int beg = rowptr[d], endp = rowptr[d + 1];
    float ad = adst[d];
    float den = 0.f;
    float4 acc = {0, 0, 0, 0};
    int idx = beg;
    for (; idx + 3 < endp; idx += 4) {
        int s0 = esrc[idx], s1 = esrc[idx + 1], s2 = esrc[idx + 2], s3 = esrc[idx + 3];
        float w0 = __expf(lrelu(asrc[s0] + ad));
        float w1 = __expf(lrelu(asrc[s1] + ad));
        float w2 = __expf(lrelu(asrc[s2] + ad));
        float w3 = __expf(lrelu(asrc[s3] + ad));
        den += (w0 + w1) + (w2 + w3);
        uint2 r0 = *reinterpret_cast<const uint2*>(h2h + (size_t)s0 * 16 + q * 4);
        uint2 r1 = *reinterpret_cast<const uint2*>(h2h + (size_t)s1 * 16 + q * 4);
        uint2 r2 = *reinterpret_cast<const uint2*>(h2h + (size_t)s2 * 16 + q * 4);
        uint2 r3 = *reinterpret_cast<const uint2*>(h2h + (size_t)s3 * 16 + q * 4);
        float2 a0 = __half22float2(*reinterpret_cast<__half2*>(&r0.x));
        float2 a1 = __half22float2(*reinterpret_cast<__half2*>(&r0.y));
        float2 b0 = __half22float2(*reinterpret_cast<__half2*>(&r1.x));
        float2 b1v = __half22float2(*reinterpret_cast<__half2*>(&r1.y));
        float2 c0 = __half22float2(*reinterpret_cast<__half2*>(&r2.x));
        float2 c1 = __half22float2(*reinterpret_cast<__half2*>(&r2.y));
        float2 e0 = __half22float2(*reinterpret_cast<__half2*>(&r3.x));
        float2 e1 = __half22float2(*reinterpret_cast<__half2*>(&r3.y));
        acc.x += (a0.x * w0 + b0.x * w1) + (c0.x * w2 + e0.x * w3);
        acc.y += (a0.y * w0 + b0.y * w1) + (c0.y * w2 + e0.y * w3);
        acc.z += (a1.x * w0 + b1v.x * w1) + (c1.x * w2 + e1.x * w3);
        acc.w += (a1.y * w0 + b1v.y * w1) + (c1.y * w2 + e1.y * w3);
    }
    for (; idx < endp; idx++) {
        int s = esrc[idx];
        float wgt = __expf(lrelu(asrc[s] + ad));
        den += wgt;
        uint2 r = *reinterpret_cast<const uint2*>(h2h + (size_t)s * 16 + q * 4);
        float2 f0 = __half22float2(*reinterpret_cast<__half2*>(&r.x));
        float2 f1 = __half22float2(*reinterpret_cast<__half2*>(&r.y));
        acc.x += f0.x * wgt; acc.y += f0.y * wgt;
        acc.z += f1.x * wgt; acc.w += f1.y * wgt;
    }
    float rr = 1.f / den;
    float4 bb = reinterpret_cast<const float4*>(b2)[q];
    float4 o;
    o.x = eluf(acc.x * rr + bb.x); o.y = eluf(acc.y * rr + bb.y);
    o.z = eluf(acc.z * rr + bb.z); o.w = eluf(acc.w * rr + bb.w);

    float v[16];
#pragma unroll
    for (int r = 0; r < 4; r++) {
        v[r * 4 + 0] = __shfl_sync(0xffffffffu, o.x, r, 4);
        v[r * 4 + 1] = __shfl_sync(0xffffffffu, o.y, r, 4);
        v[r * 4 + 2] = __shfl_sync(0xffffffffu, o.z, r, 4);
        v[r * 4 + 3] = __shfl_sync(0xffffffffu, o.w, r, 4);
    }
    float dv = rsqrtf((float)(endp - beg));
    float gacc[4];
#pragma unroll
    for (int j = 0; j < 4; j++) {
        int cc = q * 4 + j;
        float a = 0.f;
#pragma unroll
        for (int k = 0; k < 16; k++) a += v[k] * W3s[k * 16 + cc];
        gacc[j] = a * dv;
    }
    __half2 p0 = __floats2half2_rn(gacc[0], gacc[1]);
    __half2 p1 = __floats2half2_rn(gacc[2], gacc[3]);
    uint2 pk;
    pk.x = *reinterpret_cast<unsigned*>(&p0);
    pk.y = *reinterpret_cast<unsigned*>(&p1);
    *reinterpret_cast<uint2*>(gh + (size_t)d * 16 + q * 4) = pk;
}

// ----- GCN pull aggregation + finalize (fp16 gather), unroll x4 ---------------
__global__ void k_agg3(const int* __restrict__ rowptr, const int* __restrict__ esrc,
                       const __half* __restrict__ gh, const float* __restrict__ b3,
                       float* __restrict__ out, int N) {
    long long gt = (long long)blockIdx.x * blockDim.x + threadIdx.x;
    int d = (int)(gt >> 2);
    int q = threadIdx.x & 3;
    if (d >= N) return;
    int beg = rowptr[d], endp = rowptr[d + 1];
    float4 acc = {0, 0, 0, 0};
    int idx = beg;
    for (; idx + 3 < endp; idx += 4) {
        int s0 = esrc[idx], s1 = esrc[idx + 1], s2 = esrc[idx + 2], s3 = esrc[idx + 3];
        uint2 r0 = *reinterpret_cast<const uint2*>(gh + (size_t)s0 * 16 + q * 4);
        uint2 r1 = *reinterpret_cast<const uint2*>(gh + (size_t)s1 * 16 + q * 4);
        uint2 r2 = *reinterpret_cast<const uint2*>(gh + (size_t)s2 * 16 + q * 4);
        uint2 r3 = *reinterpret_cast<const uint2*>(gh + (size_t)s3 * 16 + q * 4);
        float2 a0 = __half22float2(*reinterpret_cast<__half2*>(&r0.x));
        float2 a1 = __half22float2(*reinterpret_cast<__half2*>(&r0.y));
        float2 b0 = __half22float2(*reinterpret_cast<__half2*>(&r1.x));
        float2 b1v = __half22float2(*reinterpret_cast<__half2*>(&r1.y));
        float2 c0 = __half22float2(*reinterpret_cast<__half2*>(&r2.x));
        float2 c1 = __half22float2(*reinterpret_cast<__half2*>(&r2.y));
        float2 e0 = __half22float2(*reinterpret_cast<__half2*>(&r3.x));
        float2 e1 = __half22float2(*reinterpret_cast<__half2*>(&r3.y));
        acc.x += (a0.x + b0.x) + (c0.x + e0.x);
        acc.y += (a0.y + b0.y) + (c0.y + e0.y);
        acc.z += (a1.x + b1v.x) + (c1.x + e1.x);
        acc.w += (a1.y + b1v.y) + (c1.y + e1.y);
    }
    for (; idx < endp; idx++) {
        int s = esrc[idx];
        uint2 r = *reinterpret_cast<const uint2*>(gh + (size_t)s * 16 + q * 4);
        float2 f0 = __half22float2(*reinterpret_cast<__half2*>(&r.x));
        float2 f1 = __half22float2(*reinterpret_cast<__half2*>(&r.y));
        acc.x += f0.x; acc.y += f0.y; acc.z += f1.x; acc.w += f1.y;
    }
    float dv = rsqrtf((float)(endp - beg));
    float4 bb = reinterpret_cast<const float4*>(b3)[q];
    float4 o;
    o.x = acc.x * dv + bb.x; o.y = acc.y * dv + bb.y;
    o.z = acc.z * dv + bb.z; o.w = acc.w * dv + bb.w;
    reinterpret_cast<float4*>(out + (size_t)d * 16)[q] = o;
}

// ---------------------------------------------------------------------------
extern "C" void kernel_launch(void* const* d_in, const int* in_sizes, int n_in,
                              void* d_out, int out_size) {
    const float* x      = (const float*)d_in[0];
    const int*   ei     = (const int*)d_in[1];
    const float* W1     = (const float*)d_in[2];
    const float* a_src1 = (const float*)d_in[3];
    const float* a_dst1 = (const float*)d_in[4];
    const float* b1     = (const float*)d_in[5];
    const float* W2     = (const float*)d_in[6];
    const float* a_src2 = (const float*)d_in[7];
    const float* a_dst2 = (const float*)d_in[8];
    const float* b2     = (const float*)d_in[9];
    const float* W3     = (const float*)d_in[10];
    const float* b3     = (const float*)d_in[11];
    float* out = (float*)d_out;

    const int N = in_sizes[0] / 128;
    const int E = in_sizes[1] / 2;
    const int ET = E + N;

    float *asrc1, *adst1, *asrc2, *adst2;
    __half *h1h, *out1h, *h2h, *gh, *xh, *xl, *wth, *wtl;
    int *degi, *rowptr, *esrc;
    void* p;
    cudaGetSymbolAddress(&p, g_h1h);    h1h    = (__half*)p;
    cudaGetSymbolAddress(&p, g_asrc1);  asrc1  = (float*)p;
    cudaGetSymbolAddress(&p, g_adst1);  adst1  = (float*)p;
    cudaGetSymbolAddress(&p, g_out1h);  out1h  = (__half*)p;
    cudaGetSymbolAddress(&p, g_h2h);    h2h    = (__half*)p;
    cudaGetSymbolAddress(&p, g_asrc2);  asrc2  = (float*)p;
    cudaGetSymbolAddress(&p, g_adst2);  adst2  = (float*)p;
    cudaGetSymbolAddress(&p, g_gh);     gh     = (__half*)p;
    cudaGetSymbolAddress(&p, g_degi);   degi   = (int*)p;
    cudaGetSymbolAddress(&p, g_rowptr); rowptr = (int*)p;
    cudaGetSymbolAddress(&p, g_esrc);   esrc   = (int*)p;
    cudaGetSymbolAddress(&p, g_xh);     xh     = (__half*)p;
    cudaGetSymbolAddress(&p, g_xl);     xl     = (__half*)p;
    cudaGetSymbolAddress(&p, g_wth);    wth    = (__half*)p;
    cudaGetSymbolAddress(&p, g_wtl);    wtl    = (__half*)p;

    static cudaStream_t s2 = nullptr;
    static cudaEvent_t evFork = nullptr, evJoin = nullptr, evW = nullptr;
    static int smem_set = 0;
    if (!s2) {
        cudaStreamCreateWithFlags(&s2, cudaStreamNonBlocking);
        cudaEventCreateWithFlags(&evFork, cudaEventDisableTiming);
        cudaEventCreateWithFlags(&evJoin, cudaEventDisableTiming);
        cudaEventCreateWithFlags(&evW, cudaEventDisableTiming);
    }
    if (!smem_set) {
        cudaFuncSetAttribute(k_gemm1_tc3,
                             cudaFuncAttributeMaxDynamicSharedMemorySize,
                             SMEM_H * (int)sizeof(__half));
        smem_set = 1;
    }

    const int B = 256;

    // ---- fork: W1 split + CSR chain on s2, concurrent with x split ----
    cudaEventRecord(evFork, 0);
    cudaStreamWaitEvent(s2, evFork, 0);

    k_splitW<<<(256 * 16 + B - 1) / B, B, 0, s2>>>(W1, wth, wtl);
    cudaEventRecord(evW, s2);
    cudaMemsetAsync(degi, 0, (size_t)N * sizeof(int), s2);
    k_deg<<<(ET + B - 1) / B, B, 0, s2>>>(ei, E, N, degi);
    k_scan<<<1, 1024, 0, s2>>>(degi, rowptr, N, ET);
    {
        int threads = (ET + 1) / 2;
        k_fill<<<(threads + B - 1) / B, B, 0, s2>>>(ei, E, N, rowptr, degi, esrc);
    }
    cudaEventRecord(evJoin, s2);

    // main stream: x split, then fp16-split tensor-core GEMM1 (needs wth/wtl)
    k_splitX<<<(N * 16 + B - 1) / B, B>>>(x, xh, xl, N * 16);
    cudaStreamWaitEvent(0, evW, 0);
    {
        dim3 grid((N + 127) / 128, 2);
        k_gemm1_tc3<<<grid, 256, SMEM_H * sizeof(__half)>>>(
            xh, xl, wth, wtl, a_src1, a_dst1, h1h, asrc1, adst1, N);
    }

    // ---- join: agg1 needs CSR ----
    cudaStreamWaitEvent(0, evJoin, 0);

    {
        long long tot = (long long)N * 32;   // warp per dst
        k_agg1<<<(unsigned)((tot + B - 1) / B), B>>>(rowptr, esrc, asrc1, adst1, h1h, b1, out1h, N);
    }

    // Layer 2: GAT(256 -> 16, 1 head)
    k_gemm2<<<(N + 15) / 16, B>>>(out1h, W2, a_src2, a_dst2, h2h, asrc2, adst2, N);
    {
        long long tot = (long long)N * 4;
        k_agg2<<<(unsigned)((tot + B - 1) / B), B>>>(rowptr, esrc, asrc2, adst2, h2h, b2, W3, gh, N);
    }

    // Layer 3: GCN aggregation + finalize
    {
        long long tot = (long long)N * 4;
        k_agg3<<<(unsigned)((tot + B - 1) / B), B>>>(rowptr, esrc, gh, b3, out, N);
    }
}

// round 16
// speedup vs baseline: 1.0533x; 1.0533x over previous
#include <cuda_runtime.h>
#include <cuda_fp16.h>
#include <math.h>

#define NMAX 50000
#define EMAX 800000
#define ETMAX (EMAX + NMAX)

// ---------------- scratch (device globals) -----------------------------------
__device__ __half g_h1h[NMAX * 256];
__device__ float g_asrc1[NMAX * 8];
__device__ float g_adst1[NMAX * 8];
__device__ __half g_out1h[NMAX * 256];
__device__ __half g_h2h[NMAX * 16];
__device__ float g_asrc2[NMAX];
__device__ float g_adst2[NMAX];
__device__ __half g_gh[NMAX * 16];
__device__ int   g_degi[NMAX];
__device__ int   g_rowptr[NMAX + 1];
__device__ int   g_esrc[ETMAX];
__device__ __half g_wth[256 * 128];
__device__ __half g_wtl[256 * 128];

__device__ __forceinline__ float lrelu(float x) { return x > 0.f ? x : 0.2f * x; }
__device__ __forceinline__ float eluf(float x) { return x > 0.f ? x : expm1f(x); }

// ---------------- CSR build ---------------------------------------------------
__global__ void k_deg(const int* __restrict__ ei, int E, int N, int* __restrict__ degi) {
    int e = blockIdx.x * blockDim.x + threadIdx.x;
    int ET = E + N;
    if (e >= ET) return;
    int d = (e < E) ? ei[E + e] : e - E;
    atomicAdd(&degi[d], 1);
}

// coalesced tiled exclusive scan (single block, 1024 threads)
__global__ void k_scan(const int* __restrict__ degi, int* __restrict__ rowptr,
                       int N, int ET) {
    __shared__ int warpsum[32];
    __shared__ int carry;
    int t = threadIdx.x;
    int lane = t & 31, wid = t >> 5;
    if (t == 0) carry = 0;
    __syncthreads();
    for (int base = 0; base < N; base += 1024) {
        int i = base + t;
        int v = (i < N) ? degi[i] : 0;
        int s = v;
#pragma unroll
        for (int off = 1; off < 32; off <<= 1) {
            int u = __shfl_up_sync(0xffffffffu, s, off);
            if (lane >= off) s += u;
        }
        if (lane == 31) warpsum[wid] = s;
        __syncthreads();
        if (wid == 0) {
            int ws = warpsum[lane];
#pragma unroll
            for (int off = 1; off < 32; off <<= 1) {
                int u = __shfl_up_sync(0xffffffffu, ws, off);
                if (lane >= off) ws += u;
            }
            warpsum[lane] = ws;
        }
        __syncthreads();
        int woff = (wid == 0) ? 0 : warpsum[wid - 1];
        int excl = carry + woff + s - v;
        if (i < N) rowptr[i] = excl;
        __syncthreads();
        if (t == 0) carry += warpsum[31];
        __syncthreads();
    }
    if (t == 0) rowptr[N] = ET;
}

// fill: 2 edges per thread; slot allocation via atomicSub on degi (no cursor).
__global__ void k_fill(const int* __restrict__ ei, int E, int N,
                       const int* __restrict__ rowptr, int* __restrict__ degi,
                       int* __restrict__ esrc) {
    int i = blockIdx.x * blockDim.x + threadIdx.x;
    int ET = E + N;
    int e0 = 2 * i, e1 = 2 * i + 1;
    if (e0 >= ET) return;
    int s0, d0;
    if (e0 < E) { s0 = ei[e0]; d0 = ei[E + e0]; } else { s0 = d0 = e0 - E; }
    if (e1 < ET) {
        int s1, d1;
        if (e1 < E) { s1 = ei[e1]; d1 = ei[E + e1]; } else { s1 = d1 = e1 - E; }
        int p0 = rowptr[d0] + atomicSub(&degi[d0], 1) - 1;
        int p1 = rowptr[d1] + atomicSub(&degi[d1], 1) - 1;
        esrc[p0] = s0;
        esrc[p1] = s1;
    } else {
        int p0 = rowptr[d0] + atomicSub(&degi[d0], 1) - 1;
        esrc[p0] = s0;
    }
}

// ---------------- helpers ------------------------------------------------------
__device__ __forceinline__ void mma_f16(float* d, const unsigned* a, const unsigned* b) {
    asm volatile("mma.sync.aligned.m16n8k16.row.col.f32.f16.f16.f32 "
                 "{%0,%1,%2,%3}, {%4,%5,%6,%7}, {%8,%9}, {%0,%1,%2,%3};"
                 : "+f"(d[0]), "+f"(d[1]), "+f"(d[2]), "+f"(d[3])
                 : "r"(a[0]), "r"(a[1]), "r"(a[2]), "r"(a[3]),
                   "r"(b[0]), "r"(b[1]));
}

__device__ __forceinline__ void cpasync16(void* dst, const void* src) {
    unsigned d = (unsigned)__cvta_generic_to_shared(dst);
    asm volatile("cp.async.cg.shared.global [%0], [%1], 16;" :: "r"(d), "l"(src));
}

__device__ __forceinline__ void f16split(float x, __half& hi, __half& lo) {
    hi = __float2half_rn(x);
    lo = __float2half_rn(x - __half2float(hi));
}

// split float2 -> packed (hi2, lo2) fragment regs
__device__ __forceinline__ void fragsplit(float2 v, unsigned& hreg, unsigned& lreg) {
    __half hx, lx, hy, ly;
    f16split(v.x, hx, lx);
    f16split(v.y, hy, ly);
    __half2 hh = __halves2half2(hx, hy);
    __half2 ll = __halves2half2(lx, ly);
    hreg = *reinterpret_cast<unsigned*>(&hh);
    lreg = *reinterpret_cast<unsigned*>(&ll);
}

// ---------------- split + transpose W1 ----------------------------------------
__global__ void k_splitW(const float* __restrict__ W1, __half* __restrict__ dh,
                         __half* __restrict__ dl) {
    int i = blockIdx.x * blockDim.x + threadIdx.x;
    if (i >= 256 * 16) return;
    int n = i >> 4, kq = i & 15;
    __half h[8], l[8];
#pragma unroll
    for (int j = 0; j < 8; j++)
        f16split(W1[(kq * 8 + j) * 256 + n], h[j], l[j]);
    *reinterpret_cast<uint4*>(dh + (size_t)n * 128 + kq * 8) = *reinterpret_cast<uint4*>(h);
    *reinterpret_cast<uint4*>(dl + (size_t)n * 128 + kq * 8) = *reinterpret_cast<uint4*>(l);
}

// ---------------- GEMM1 (in-kernel fp16 split of A, m16n8k16, fused alpha) ----
// block tile 128m x 128n, 8 warps (2x4), warp tile 64x32, k-chunk 16, 2 stages
// smem per stage: A f32 plane 128x24 floats (12288B) + Bh/Bl half planes
// 128x24 halves (6144B each) = 24576B; 2 stages = 49152B.
#define ASTRF 24
#define BSTRH 24
#define A_BYTES (128 * ASTRF * 4)
#define B_BYTES (128 * BSTRH * 2)
#define STAGE_B (A_BYTES + 2 * B_BYTES)
#define SMEM_B  (2 * STAGE_B)

__global__ __launch_bounds__(256) void k_gemm1_tc4(
        const float* __restrict__ x,
        const __half* __restrict__ wth, const __half* __restrict__ wtl,
        const float* __restrict__ a_src, const float* __restrict__ a_dst,
        __half* __restrict__ h1h, float* __restrict__ asrcn, float* __restrict__ adstn,
        int N) {
    extern __shared__ char smc[];
    const int t = threadIdx.x;
    const int warp = t >> 5, lane = t & 31;
    const int wm = warp >> 2, wn = warp & 3;
    const int lm = lane >> 2, lk = lane & 3;
    const int r0 = blockIdx.x * 128;
    const int n0 = blockIdx.y * 128;

    float acc[4][4][4];
#pragma unroll
    for (int i = 0; i < 4; i++)
#pragma unroll
        for (int j = 0; j < 4; j++)
#pragma unroll
            for (int v = 0; v < 4; v++) acc[i][j][v] = 0.f;

    auto issue = [&](int c, int buf) {
        int k0 = c * 16;
        char* base = smc + buf * STAGE_B;
        // A: f32, 128 rows x 16 k = 512 x 16B ops, 2 per thread
#pragma unroll
        for (int i = 0; i < 2; i++) {
            int op = t + i * 256;
            int row = op >> 2, seg = op & 3;
            int gr = r0 + row; if (gr > N - 1) gr = N - 1;
            cpasync16(base + (row * ASTRF + seg * 4) * 4,
                      x + (size_t)gr * 128 + k0 + seg * 4);
        }
        // Bh / Bl: halves, 128 rows x 16 k = 256 x 16B ops each, 1 per thread
        {
            int row = t >> 1, seg = t & 1;
            cpasync16(base + A_BYTES + (row * BSTRH + seg * 8) * 2,
                      wth + (size_t)(n0 + row) * 128 + k0 + seg * 8);
            cpasync16(base + A_BYTES + B_BYTES + (row * BSTRH + seg * 8) * 2,
                      wtl + (size_t)(n0 + row) * 128 + k0 + seg * 8);
        }
        asm volatile("cp.async.commit_group;");
    };

    issue(0, 0);
    for (int c = 0; c < 8; c++) {
        int buf = c & 1;
        if (c < 7) {
            issue(c + 1, buf ^ 1);
            asm volatile("cp.async.wait_group 1;");
        } else {
            asm volatile("cp.async.wait_group 0;");
        }
        __syncthreads();
        const float* As = reinterpret_cast<const float*>(smc + buf * STAGE_B);
        const __half* Bh = reinterpret_cast<const __half*>(smc + buf * STAGE_B + A_BYTES);
        const __half* Bl = reinterpret_cast<const __half*>(smc + buf * STAGE_B + A_BYTES + B_BYTES);
        const int kb = lk * 2;

        unsigned Ahf[4][4], Alf[4][4];
#pragma unroll
        for (int mt = 0; mt < 4; mt++) {
            int mrow = wm * 64 + mt * 16 + lm;
            float2 v0 = *reinterpret_cast<const float2*>(As + mrow * ASTRF + kb);
            float2 v1 = *reinterpret_cast<const float2*>(As + (mrow + 8) * ASTRF + kb);
            float2 v2 = *reinterpret_cast<const float2*>(As + mrow * ASTRF + kb + 8);
            float2 v3 = *reinterpret_cast<const float2*>(As + (mrow + 8) * ASTRF + kb + 8);
            fragsplit(v0, Ahf[mt][0], Alf[mt][0]);
            fragsplit(v1, Ahf[mt][1], Alf[mt][1]);
            fragsplit(v2, Ahf[mt][2], Alf[mt][2]);
            fragsplit(v3, Ahf[mt][3], Alf[mt][3]);
        }
        unsigned Bhf[4][2], Blf[4][2];
#pragma unroll
        for (int nt = 0; nt < 4; nt++) {
            int n = wn * 32 + nt * 8 + lm;
            Bhf[nt][0] = *reinterpret_cast<const unsigned*>(Bh + n * BSTRH + kb);
            Bhf[nt][1] = *reinterpret_cast<const unsigned*>(Bh + n * BSTRH + kb + 8);
            Blf[nt][0] = *reinterpret_cast<const unsigned*>(Bl + n * BSTRH + kb);
            Blf[nt][1] = *reinterpret_cast<const unsigned*>(Bl + n * BSTRH + kb + 8);
        }
#pragma unroll
        for (int mt = 0; mt < 4; mt++)
#pragma unroll
            for (int nt = 0; nt < 4; nt++) {
                mma_f16(acc[mt][nt], Ahf[mt], Bhf[nt]);
                mma_f16(acc[mt][nt], Ahf[mt], Blf[nt]);
                mma_f16(acc[mt][nt], Alf[mt], Bhf[nt]);
            }
        __syncthreads();
    }

    // ---- epilogue: store h1 (fp16) + fused alpha projections ----
    const int h = blockIdx.y * 4 + wn;
    float2 asv[4], adv[4];
#pragma unroll
    for (int nt = 0; nt < 4; nt++) {
        asv[nt] = *reinterpret_cast<const float2*>(a_src + h * 32 + nt * 8 + lk * 2);
        adv[nt] = *reinterpret_cast<const float2*>(a_dst + h * 32 + nt * 8 + lk * 2);
    }
#pragma unroll
    for (int mt = 0; mt < 4; mt++) {
        int row1 = r0 + wm * 64 + mt * 16 + lm;
        int row2 = row1 + 8;
        float s1 = 0.f, d1 = 0.f, s2 = 0.f, d2 = 0.f;
#pragma unroll
        for (int nt = 0; nt < 4; nt++) {
            int col = n0 + wn * 32 + nt * 8 + lk * 2;
            s1 += acc[mt][nt][0] * asv[nt].x + acc[mt][nt][1] * asv[nt].y;
            d1 += acc[mt][nt][0] * adv[nt].x + acc[mt][nt][1] * adv[nt].y;
            s2 += acc[mt][nt][2] * asv[nt].x + acc[mt][nt][3] * asv[nt].y;
            d2 += acc[mt][nt][2] * adv[nt].x + acc[mt][nt][3] * adv[nt].y;
            if (row1 < N)
                *reinterpret_cast<__half2*>(h1h + (size_t)row1 * 256 + col) =
                    __floats2half2_rn(acc[mt][nt][0], acc[mt][nt][1]);
            if (row2 < N)
                *reinterpret_cast<__half2*>(h1h + (size_t)row2 * 256 + col) =
                    __floats2half2_rn(acc[mt][nt][2], acc[mt][nt][3]);
        }
        s1 += __shfl_xor_sync(0xffffffffu, s1, 1); s1 += __shfl_xor_sync(0xffffffffu, s1, 2);
        d1 += __shfl_xor_sync(0xffffffffu, d1, 1); d1 += __shfl_xor_sync(0xffffffffu, d1, 2);
        s2 += __shfl_xor_sync(0xffffffffu, s2, 1); s2 += __shfl_xor_sync(0xffffffffu, s2, 2);
        d2 += __shfl_xor_sync(0xffffffffu, d2, 1); d2 += __shfl_xor_sync(0xffffffffu, d2, 2);
        if (lk == 0) {
            if (row1 < N) { asrcn[row1 * 8 + h] = s1; adstn[row1 * 8 + h] = d1; }
            if (row2 < N) { asrcn[row2 * 8 + h] = s2; adstn[row2 * 8 + h] = d2; }
        }
    }
}

// ----- GAT1 pull aggregation: warp per dst, per-lane head weights, unroll x4 --
__global__ void k_agg1(const int* __restrict__ rowptr, const int* __restrict__ esrc,
                       const float* __restrict__ asrc, const float* __restrict__ adst,
                       const __half* __restrict__ h1h, const float* __restrict__ b1,
                       __half* __restrict__ out1h, int N) {
    int d = (int)(((long long)blockIdx.x * blockDim.x + threadIdx.x) >> 5);
    int lane = threadIdx.x & 31;
    if (d >= N) return;
    int beg = rowptr[d], endp = rowptr[d + 1];
    const int h0 = lane >> 2;
    float ad = adst[d * 8 + h0];
    float den = 0.f;
    float accv[8];
#pragma unroll
    for (int i = 0; i < 8; i++) accv[i] = 0.f;
    for (int base = beg; base < endp; base += 32) {
        int nn = min(32, endp - base);
        int sreg = (base + lane < endp) ? esrc[base + lane] : 0;
        int j = 0;
        for (; j + 3 < nn; j += 4) {
            int s0 = __shfl_sync(0xffffffffu, sreg, j);
            int s1 = __shfl_sync(0xffffffffu, sreg, j + 1);
            int s2 = __shfl_sync(0xffffffffu, sreg, j + 2);
            int s3 = __shfl_sync(0xffffffffu, sreg, j + 3);
            float w0 = __expf(lrelu(asrc[s0 * 8 + h0] + ad));
            float w1 = __expf(lrelu(asrc[s1 * 8 + h0] + ad));
            float w2 = __expf(lrelu(asrc[s2 * 8 + h0] + ad));
            float w3 = __expf(lrelu(asrc[s3 * 8 + h0] + ad));
            den += (w0 + w1) + (w2 + w3);
            uint4 r0 = *reinterpret_cast<const uint4*>(h1h + (size_t)s0 * 256 + lane * 8);
            uint4 r1 = *reinterpret_cast<const uint4*>(h1h + (size_t)s1 * 256 + lane * 8);
            uint4 r2 = *reinterpret_cast<const uint4*>(h1h + (size_t)s2 * 256 + lane * 8);
            uint4 r3 = *reinterpret_cast<const uint4*>(h1h + (size_t)s3 * 256 + lane * 8);
            {
                float2 f0 = __half22float2(*reinterpret_cast<__half2*>(&r0.x));
                float2 f1 = __half22float2(*reinterpret_cast<__half2*>(&r0.y));
                float2 f2 = __half22float2(*reinterpret_cast<__half2*>(&r0.z));
                float2 f3 = __half22float2(*reinterpret_cast<__half2*>(&r0.w));
                accv[0] += f0.x * w0; accv[1] += f0.y * w0;
                accv[2] += f1.x * w0; accv[3] += f1.y * w0;
                accv[4] += f2.x * w0; accv[5] += f2.y * w0;
                accv[6] += f3.x * w0; accv[7] += f3.y * w0;
            }
            {
                float2 f0 = __half22float2(*reinterpret_cast<__half2*>(&r1.x));
                float2 f1 = __half22float2(*reinterpret_cast<__half2*>(&r1.y));
                float2 f2 = __half22float2(*reinterpret_cast<__half2*>(&r1.z));
                float2 f3 = __half22float2(*reinterpret_cast<__half2*>(&r1.w));
                accv[0] += f0.x * w1; accv[1] += f0.y * w1;
                accv[2] += f1.x * w1; accv[3] += f1.y * w1;
                accv[4] += f2.x * w1; accv[5] += f2.y * w1;
                accv[6] += f3.x * w1; accv[7] += f3.y * w1;
            }
            {
                float2 f0 = __half22float2(*reinterpret_cast<__half2*>(&r2.x));
                float2 f1 = __half22float2(*reinterpret_cast<__half2*>(&r2.y));
                float2 f2 = __half22float2(*reinterpret_cast<__half2*>(&r2.z));
                float2 f3 = __half22float2(*reinterpret_cast<__half2*>(&r2.w));
                accv[0] += f0.x * w2; accv[1] += f0.y * w2;
                accv[2] += f1.x * w2; accv[3] += f1.y * w2;
                accv[4] += f2.x * w2; accv[5] += f2.y * w2;
                accv[6] += f3.x * w2; accv[7] += f3.y * w2;
            }
            {
                float2 f0 = __half22float2(*reinterpret_cast<__half2*>(&r3.x));
                float2 f1 = __half22float2(*reinterpret_cast<__half2*>(&r3.y));
                float2 f2 = __half22float2(*reinterpret_cast<__half2*>(&r3.z));
                float2 f3 = __half22float2(*reinterpret_cast<__half2*>(&r3.w));
                accv[0] += f0.x * w3; accv[1] += f0.y * w3;
                accv[2] += f1.x * w3; accv[3] += f1.y * w3;
                accv[4] += f2.x * w3; accv[5] += f2.y * w3;
                accv[6] += f3.x * w3; accv[7] += f3.y * w3;
            }
        }
        for (; j < nn; j++) {
            int s = __shfl_sync(0xffffffffu, sreg, j);
            float a = __expf(lrelu(asrc[s * 8 + h0] + ad));
            den += a;
            uint4 r = *reinterpret_cast<const uint4*>(h1h + (size_t)s * 256 + lane * 8);
            float2 f0 = __half22float2(*reinterpret_cast<__half2*>(&r.x));
            float2 f1 = __half22float2(*reinterpret_cast<__half2*>(&r.y));
            float2 f2 = __half22float2(*reinterpret_cast<__half2*>(&r.z));
            float2 f3 = __half22float2(*reinterpret_cast<__half2*>(&r.w));
            accv[0] += f0.x * a; accv[1] += f0.y * a;
            accv[2] += f1.x * a; accv[3] += f1.y * a;
            accv[4] += f2.x * a; accv[5] += f2.y * a;
            accv[6] += f3.x * a; accv[7] += f3.y * a;
        }
    }
    float rs = 1.f / den;
    const float4* bp = reinterpret_cast<const float4*>(b1 + lane * 8);
    float4 bb0 = bp[0], bb1 = bp[1];
    float o[8];
    o[0] = eluf(accv[0] * rs + bb0.x); o[1] = eluf(accv[1] * rs + bb0.y);
    o[2] = eluf(accv[2] * rs + bb0.z); o[3] = eluf(accv[3] * rs + bb0.w);
    o[4] = eluf(accv[4] * rs + bb1.x); o[5] = eluf(accv[5] * rs + bb1.y);
    o[6] = eluf(accv[6] * rs + bb1.z); o[7] = eluf(accv[7] * rs + bb1.w);
    __half2 p0 = __floats2half2_rn(o[0], o[1]);
    __half2 p1 = __floats2half2_rn(o[2], o[3]);
    __half2 p2 = __floats2half2_rn(o[4], o[5]);
    __half2 p3 = __floats2half2_rn(o[6], o[7]);
    uint4 pk;
    pk.x = *reinterpret_cast<unsigned*>(&p0);
    pk.y = *reinterpret_cast<unsigned*>(&p1);
    pk.z = *reinterpret_cast<unsigned*>(&p2);
    pk.w = *reinterpret_cast<unsigned*>(&p3);
    *reinterpret_cast<uint4*>(out1h + (size_t)d * 256 + lane * 8) = pk;
}

// ----- GEMM2: h2 = x2[N,256] @ W2[256,16], fp16 in (uint4), fused alpha2 -----
__global__ void k_gemm2(const __half* __restrict__ x2h, const float* __restrict__ W2,
                        const float* __restrict__ a_src2, const float* __restrict__ a_dst2,
                        __half* __restrict__ h2h, float* __restrict__ asrc2n,
                        float* __restrict__ adst2n, int N) {
    __shared__ float Wsh[256 * 16];
    int t = threadIdx.x;
    for (int i = t; i < 4096; i += 256) Wsh[i] = W2[i];
    __syncthreads();
    int n = blockIdx.x * 16 + (t >> 4);
    int c = t & 15;
    if (n >= N) return;
    float acc = 0.f;
    const uint4* xr4 = reinterpret_cast<const uint4*>(x2h + (size_t)n * 256);
#pragma unroll 8
    for (int kq = 0; kq < 32; kq++) {
        uint4 r = xr4[kq];
        float2 f0 = __half22float2(*reinterpret_cast<__half2*>(&r.x));
        float2 f1 = __half22float2(*reinterpret_cast<__half2*>(&r.y));
        float2 f2 = __half22float2(*reinterpret_cast<__half2*>(&r.z));
        float2 f3 = __half22float2(*reinterpret_cast<__half2*>(&r.w));
        const float* wb = Wsh + (kq * 8) * 16 + c;
        acc += f0.x * wb[0]   + f0.y * wb[16]
             + f1.x * wb[32]  + f1.y * wb[48]
             + f2.x * wb[64]  + f2.y * wb[80]
             + f3.x * wb[96]  + f3.y * wb[112];
    }
    h2h[(size_t)n * 16 + c] = __float2half(acc);
    float r1 = acc * a_src2[c];
    float r2 = acc * a_dst2[c];
#pragma unroll
    for (int m = 8; m >= 1; m >>= 1) {
        r1 += __shfl_xor_sync(0xffffffffu, r1, m, 16);
        r2 += __shfl_xor_sync(0xffffffffu, r2, m, 16);
    }
    if (c == 0) { asrc2n[n] = r1; adst2n[n] = r2; }
}

// ----- GAT2 pull aggregation + fused GCN transform (h3), unroll x4 -----------
__global__ void k_agg2(const int* __restrict__ rowptr, const int* __restrict__ esrc,
                       const float* __restrict__ asrc, const float* __restrict__ adst,
                       const __half* __restrict__ h2h, const float* __restrict__ b2,
                       const float* __restrict__ W3, __half* __restrict__ gh, int N) {
    __shared__ float W3s[256];
    if (threadIdx.x < 256) W3s[threadIdx.x] = W3[threadIdx.x];
    __syncthreads();
    long long gt = (long long)blockIdx.x * blockDim.x + threadIdx.x;
    int d = (int)(gt >> 2);
    int q = threadIdx.x & 3;
    if (d >= N) return;
    int beg = rowptr[d], endp = rowptr[d + 1];
    float ad = adst[d];
    float den = 0.f;
    float4 acc = {0, 0, 0, 0};
    int idx = beg;
    for (; idx + 3 < endp; idx += 4) {
        int s0 = esrc[idx], s1 = esrc[idx + 1], s2 = esrc[idx + 2], s3 = esrc[idx + 3];
        float w0 = __expf(lrelu(asrc[s0] + ad));
        float w1 = __expf(lrelu(asrc[s1] + ad));
        float w2 = __expf(lrelu(asrc[s2] + ad));
        float w3 = __expf(lrelu(asrc[s3] + ad));
        den += (w0 + w1) + (w2 + w3);
        uint2 r0 = *reinterpret_cast<const uint2*>(h2h + (size_t)s0 * 16 + q * 4);
        uint2 r1 = *reinterpret_cast<const uint2*>(h2h + (size_t)s1 * 16 + q * 4);
        uint2 r2 = *reinterpret_cast<const uint2*>(h2h + (size_t)s2 * 16 + q * 4);
        uint2 r3 = *reinterpret_cast<const uint2*>(h2h + (size_t)s3 * 16 + q * 4);
        float2 a0 = __half22float2(*reinterpret_cast<__half2*>(&r0.x));
        float2 a1 = __half22float2(*reinterpret_cast<__half2*>(&r0.y));
        float2 b0 = __half22float2(*reinterpret_cast<__half2*>(&r1.x));
        float2 b1v = __half22float2(*reinterpret_cast<__half2*>(&r1.y));
        float2 c0 = __half22float2(*reinterpret_cast<__half2*>(&r2.x));
        float2 c1 = __half22float2(*reinterpret_cast<__half2*>(&r2.y));
        float2 e0 = __half22float2(*reinterpret_cast<__half2*>(&r3.x));
        float2 e1 = __half22float2(*reinterpret_cast<__half2*>(&r3.y));
        acc.x += (a0.x * w0 + b0.x * w1) + (c0.x * w2 + e0.x * w3);
        acc.y += (a0.y * w0 + b0.y * w1) + (c0.y * w2 + e0.y * w3);
        acc.z += (a1.x * w0 + b1v.x * w1) + (c1.x * w2 + e1.x * w3);
        acc.w += (a1.y * w0 + b1v.y * w1) + (c1.y * w2 + e1.y * w3);
    }
    for (; idx < endp; idx++) {
        int s = esrc[idx];
        float wgt = __expf(lrelu(asrc[s] + ad));
        den += wgt;
        uint2 r = *reinterpret_cast<const uint2*>(h2h + (size_t)s * 16 + q * 4);
        float2 f0 = __half22float2(*reinterpret_cast<__half2*>(&r.x));
        float2 f1 = __half22float2(*reinterpret_cast<__half2*>(&r.y));
        acc.x += f0.x * wgt; acc.y += f0.y * wgt;
        acc.z += f1.x * wgt; acc.w += f1.y * wgt;
    }
    float rr = 1.f / den;
    float4 bb = reinterpret_cast<const float4*>(b2)[q];
    float4 o;
    o.x = eluf(acc.x * rr + bb.x); o.y = eluf(acc.y * rr + bb.y);
    o.z = eluf(acc.z * rr + bb.z); o.w = eluf(acc.w * rr + bb.w);

    float v[16];
#pragma unroll
    for (int r = 0; r < 4; r++) {
        v[r * 4 + 0] = __shfl_sync(0xffffffffu, o.x, r, 4);
        v[r * 4 + 1] = __shfl_sync(0xffffffffu, o.y, r, 4);
        v[r * 4 + 2] = __shfl_sync(0xffffffffu, o.z, r, 4);
        v[r * 4 + 3] = __shfl_sync(0xffffffffu, o.w, r, 4);
    }
    float dv = rsqrtf((float)(endp - beg));
    float gacc[4];
#pragma unroll
    for (int j = 0; j < 4; j++) {
        int cc = q * 4 + j;
        float a = 0.f;
#pragma unroll
        for (int k = 0; k < 16; k++) a += v[k] * W3s[k * 16 + cc];
        gacc[j] = a * dv;
    }
    __half2 p0 = __floats2half2_rn(gacc[0], gacc[1]);
    __half2 p1 = __floats2half2_rn(gacc[2], gacc[3]);
    uint2 pk;
    pk.x = *reinterpret_cast<unsigned*>(&p0);
    pk.y = *reinterpret_cast<unsigned*>(&p1);
    *reinterpret_cast<uint2*>(gh + (size_t)d * 16 + q * 4) = pk;
}

// ----- GCN pull aggregation + finalize (fp16 gather), unroll x4 ---------------
__global__ void k_agg3(const int* __restrict__ rowptr, const int* __restrict__ esrc,
                       const __half* __restrict__ gh, const float* __restrict__ b3,
                       float* __restrict__ out, int N) {
    long long gt = (long long)blockIdx.x * blockDim.x + threadIdx.x;
    int d = (int)(gt >> 2);
    int q = threadIdx.x & 3;
    if (d >= N) return;
    int beg = rowptr[d], endp = rowptr[d + 1];
    float4 acc = {0, 0, 0, 0};
    int idx = beg;
    for (; idx + 3 < endp; idx += 4) {
        int s0 = esrc[idx], s1 = esrc[idx + 1], s2 = esrc[idx + 2], s3 = esrc[idx + 3];
        uint2 r0 = *reinterpret_cast<const uint2*>(gh + (size_t)s0 * 16 + q * 4);
        uint2 r1 = *reinterpret_cast<const uint2*>(gh + (size_t)s1 * 16 + q * 4);
        uint2 r2 = *reinterpret_cast<const uint2*>(gh + (size_t)s2 * 16 + q * 4);
        uint2 r3 = *reinterpret_cast<const uint2*>(gh + (size_t)s3 * 16 + q * 4);
        float2 a0 = __half22float2(*reinterpret_cast<__half2*>(&r0.x));
        float2 a1 = __half22float2(*reinterpret_cast<__half2*>(&r0.y));
        float2 b0 = __half22float2(*reinterpret_cast<__half2*>(&r1.x));
        float2 b1v = __half22float2(*reinterpret_cast<__half2*>(&r1.y));
        float2 c0 = __half22float2(*reinterpret_cast<__half2*>(&r2.x));
        float2 c1 = __half22float2(*reinterpret_cast<__half2*>(&r2.y));
        float2 e0 = __half22float2(*reinterpret_cast<__half2*>(&r3.x));
        float2 e1 = __half22float2(*reinterpret_cast<__half2*>(&r3.y));
        acc.x += (a0.x + b0.x) + (c0.x + e0.x);
        acc.y += (a0.y + b0.y) + (c0.y + e0.y);
        acc.z += (a1.x + b1v.x) + (c1.x + e1.x);
        acc.w += (a1.y + b1v.y) + (c1.y + e1.y);
    }
    for (; idx < endp; idx++) {
        int s = esrc[idx];
        uint2 r = *reinterpret_cast<const uint2*>(gh + (size_t)s * 16 + q * 4);
        float2 f0 = __half22float2(*reinterpret_cast<__half2*>(&r.x));
        float2 f1 = __half22float2(*reinterpret_cast<__half2*>(&r.y));
        acc.x += f0.x; acc.y += f0.y; acc.z += f1.x; acc.w += f1.y;
    }
    float dv = rsqrtf((float)(endp - beg));
    float4 bb = reinterpret_cast<const float4*>(b3)[q];
    float4 o;
    o.x = acc.x * dv + bb.x; o.y = acc.y * dv + bb.y;
    o.z = acc.z * dv + bb.z; o.w = acc.w * dv + bb.w;
    reinterpret_cast<float4*>(out + (size_t)d * 16)[q] = o;
}

// ---------------------------------------------------------------------------
extern "C" void kernel_launch(void* const* d_in, const int* in_sizes, int n_in,
                              void* d_out, int out_size) {
    const float* x      = (const float*)d_in[0];
    const int*   ei     = (const int*)d_in[1];
    const float* W1     = (const float*)d_in[2];
    const float* a_src1 = (const float*)d_in[3];
    const float* a_dst1 = (const float*)d_in[4];
    const float* b1     = (const float*)d_in[5];
    const float* W2     = (const float*)d_in[6];
    const float* a_src2 = (const float*)d_in[7];
    const float* a_dst2 = (const float*)d_in[8];
    const float* b2     = (const float*)d_in[9];
    const float* W3     = (const float*)d_in[10];
    const float* b3     = (const float*)d_in[11];
    float* out = (float*)d_out;

    const int N = in_sizes[0] / 128;
    const int E = in_sizes[1] / 2;
    const int ET = E + N;

    float *asrc1, *adst1, *asrc2, *adst2;
    __half *h1h, *out1h, *h2h, *gh, *wth, *wtl;
    int *degi, *rowptr, *esrc;
    void* p;
    cudaGetSymbolAddress(&p, g_h1h);    h1h    = (__half*)p;
    cudaGetSymbolAddress(&p, g_asrc1);  asrc1  = (float*)p;
    cudaGetSymbolAddress(&p, g_adst1);  adst1  = (float*)p;
    cudaGetSymbolAddress(&p, g_out1h);  out1h  = (__half*)p;
    cudaGetSymbolAddress(&p, g_h2h);    h2h    = (__half*)p;
    cudaGetSymbolAddress(&p, g_asrc2);  asrc2  = (float*)p;
    cudaGetSymbolAddress(&p, g_adst2);  adst2  = (float*)p;
    cudaGetSymbolAddress(&p, g_gh);     gh     = (__half*)p;
    cudaGetSymbolAddress(&p, g_degi);   degi   = (int*)p;
    cudaGetSymbolAddress(&p, g_rowptr); rowptr = (int*)p;
    cudaGetSymbolAddress(&p, g_esrc);   esrc   = (int*)p;
    cudaGetSymbolAddress(&p, g_wth);    wth    = (__half*)p;
    cudaGetSymbolAddress(&p, g_wtl);    wtl    = (__half*)p;

    static cudaStream_t s2 = nullptr;
    static cudaEvent_t evFork = nullptr, evJoin = nullptr, evW = nullptr;
    static int smem_set = 0;
    if (!s2) {
        cudaStreamCreateWithFlags(&s2, cudaStreamNonBlocking);
        cudaEventCreateWithFlags(&evFork, cudaEventDisableTiming);
        cudaEventCreateWithFlags(&evJoin, cudaEventDisableTiming);
        cudaEventCreateWithFlags(&evW, cudaEventDisableTiming);
    }
    if (!smem_set) {
        cudaFuncSetAttribute(k_gemm1_tc4,
                             cudaFuncAttributeMaxDynamicSharedMemorySize, SMEM_B);
        smem_set = 1;
    }

    const int B = 256;

    // ---- fork: W1 split + CSR chain on s2 ----
    cudaEventRecord(evFork, 0);
    cudaStreamWaitEvent(s2, evFork, 0);

    k_splitW<<<(256 * 16 + B - 1) / B, B, 0, s2>>>(W1, wth, wtl);
    cudaEventRecord(evW, s2);
    cudaMemsetAsync(degi, 0, (size_t)N * sizeof(int), s2);
    k_deg<<<(ET + B - 1) / B, B, 0, s2>>>(ei, E, N, degi);
    k_scan<<<1, 1024, 0, s2>>>(degi, rowptr, N, ET);
    {
        int threads = (ET + 1) / 2;
        k_fill<<<(threads + B - 1) / B, B, 0, s2>>>(ei, E, N, rowptr, degi, esrc);
    }
    cudaEventRecord(evJoin, s2);

    // main stream: tensor-core GEMM1 reads x (f32) directly; needs wth/wtl
    cudaStreamWaitEvent(0, evW, 0);
    {
        dim3 grid((N + 127) / 128, 2);
        k_gemm1_tc4<<<grid, 256, SMEM_B>>>(
            x, wth, wtl, a_src1, a_dst1, h1h, asrc1, adst1, N);
    }

    // ---- join: agg1 needs CSR ----
    cudaStreamWaitEvent(0, evJoin, 0);

    {
        long long tot = (long long)N * 32;   // warp per dst
        k_agg1<<<(unsigned)((tot + B - 1) / B), B>>>(rowptr, esrc, asrc1, adst1, h1h, b1, out1h, N);
    }

    // Layer 2: GAT(256 -> 16, 1 head)
    k_gemm2<<<(N + 15) / 16, B>>>(out1h, W2, a_src2, a_dst2, h2h, asrc2, adst2, N);
    {
        long long tot = (long long)N * 4;
        k_agg2<<<(unsigned)((tot + B - 1) / B), B>>>(rowptr, esrc, asrc2, adst2, h2h, b2, W3, gh, N);
    }

    // Layer 3: GCN aggregation + finalize
    {
        long long tot = (long long)N * 4;
        k_agg3<<<(unsigned)((tot + B - 1) / B), B>>>(rowptr, esrc, gh, b3, out, N);
    }
}

// round 17
// speedup vs baseline: 1.0822x; 1.0275x over previous
#include <cuda_runtime.h>
#include <cuda_fp16.h>
#include <math.h>

#define NMAX 50000
#define EMAX 800000
#define ETMAX (EMAX + NMAX)

// ---------------- scratch (device globals) -----------------------------------
__device__ __half g_h1h[NMAX * 256];
__device__ float g_asrc1[NMAX * 8];
__device__ float g_adst1[NMAX * 8];
__device__ __half g_out1h[NMAX * 256];
__device__ __half g_h2h[NMAX * 16];
__device__ float g_asrc2[NMAX];
__device__ float g_adst2[NMAX];
__device__ __half g_gh[NMAX * 16];
__device__ int   g_degi[NMAX];
__device__ int   g_cursor[NMAX];
__device__ int   g_rowptr[NMAX + 1];
__device__ int   g_esrc[ETMAX];
__device__ __half g_wt[256 * 128];      // W1^T fp16 ([n][k]), single plane

__device__ __forceinline__ float lrelu(float x) { return x > 0.f ? x : 0.2f * x; }
__device__ __forceinline__ float eluf(float x) { return x > 0.f ? x : expm1f(x); }

// ---------------- CSR build ---------------------------------------------------
__global__ void k_deg(const int* __restrict__ ei, int E, int N, int* __restrict__ degi) {
    int e = blockIdx.x * blockDim.x + threadIdx.x;
    int ET = E + N;
    if (e >= ET) return;
    int d = (e < E) ? ei[E + e] : e - E;
    atomicAdd(&degi[d], 1);
}

// coalesced tiled exclusive scan; writes rowptr AND cursor (= rowptr copy)
__global__ void k_scan(const int* __restrict__ degi, int* __restrict__ rowptr,
                       int* __restrict__ cursor, int N, int ET) {
    __shared__ int warpsum[32];
    __shared__ int carry;
    int t = threadIdx.x;
    int lane = t & 31, wid = t >> 5;
    if (t == 0) carry = 0;
    __syncthreads();
    for (int base = 0; base < N; base += 1024) {
        int i = base + t;
        int v = (i < N) ? degi[i] : 0;
        int s = v;
#pragma unroll
        for (int off = 1; off < 32; off <<= 1) {
            int u = __shfl_up_sync(0xffffffffu, s, off);
            if (lane >= off) s += u;
        }
        if (lane == 31) warpsum[wid] = s;
        __syncthreads();
        if (wid == 0) {
            int ws = warpsum[lane];
#pragma unroll
            for (int off = 1; off < 32; off <<= 1) {
                int u = __shfl_up_sync(0xffffffffu, ws, off);
                if (lane >= off) ws += u;
            }
            warpsum[lane] = ws;
        }
        __syncthreads();
        int woff = (wid == 0) ? 0 : warpsum[wid - 1];
        int excl = carry + woff + s - v;
        if (i < N) { rowptr[i] = excl; cursor[i] = excl; }
        __syncthreads();
        if (t == 0) carry += warpsum[31];
        __syncthreads();
    }
    if (t == 0) rowptr[N] = ET;
}

// fill: 2 edges per thread; single atomicAdd on cursor (no rowptr load).
__global__ void k_fill(const int* __restrict__ ei, int E, int N,
                       int* __restrict__ cursor, int* __restrict__ esrc) {
    int i = blockIdx.x * blockDim.x + threadIdx.x;
    int ET = E + N;
    int e0 = 2 * i, e1 = 2 * i + 1;
    if (e0 >= ET) return;
    int s0, d0;
    if (e0 < E) { s0 = ei[e0]; d0 = ei[E + e0]; } else { s0 = d0 = e0 - E; }
    if (e1 < ET) {
        int s1, d1;
        if (e1 < E) { s1 = ei[e1]; d1 = ei[E + e1]; } else { s1 = d1 = e1 - E; }
        int p0 = atomicAdd(&cursor[d0], 1);
        int p1 = atomicAdd(&cursor[d1], 1);
        esrc[p0] = s0;
        esrc[p1] = s1;
    } else {
        int p0 = atomicAdd(&cursor[d0], 1);
        esrc[p0] = s0;
    }
}

// ---------------- helpers ------------------------------------------------------
__device__ __forceinline__ void mma_f16(float* d, const unsigned* a, const unsigned* b) {
    asm volatile("mma.sync.aligned.m16n8k16.row.col.f32.f16.f16.f32 "
                 "{%0,%1,%2,%3}, {%4,%5,%6,%7}, {%8,%9}, {%0,%1,%2,%3};"
                 : "+f"(d[0]), "+f"(d[1]), "+f"(d[2]), "+f"(d[3])
                 : "r"(a[0]), "r"(a[1]), "r"(a[2]), "r"(a[3]),
                   "r"(b[0]), "r"(b[1]));
}

__device__ __forceinline__ void cpasync16(void* dst, const void* src) {
    unsigned d = (unsigned)__cvta_generic_to_shared(dst);
    asm volatile("cp.async.cg.shared.global [%0], [%1], 16;" :: "r"(d), "l"(src));
}

__device__ __forceinline__ void f16split(float x, __half& hi, __half& lo) {
    hi = __float2half_rn(x);
    lo = __float2half_rn(x - __half2float(hi));
}

// split float2 -> packed (hi2, lo2) fragment regs
__device__ __forceinline__ void fragsplit(float2 v, unsigned& hreg, unsigned& lreg) {
    __half hx, lx, hy, ly;
    f16split(v.x, hx, lx);
    f16split(v.y, hy, ly);
    __half2 hh = __halves2half2(hx, hy);
    __half2 ll = __halves2half2(lx, ly);
    hreg = *reinterpret_cast<unsigned*>(&hh);
    lreg = *reinterpret_cast<unsigned*>(&ll);
}

// ---------------- transpose+convert W1: [128][256] f32 -> [256][128] fp16 -----
__global__ void k_splitW(const float* __restrict__ W1, __half* __restrict__ dh) {
    int i = blockIdx.x * blockDim.x + threadIdx.x;
    if (i >= 256 * 16) return;
    int n = i >> 4, kq = i & 15;
    __half h[8];
#pragma unroll
    for (int j = 0; j < 8; j++)
        h[j] = __float2half_rn(W1[(kq * 8 + j) * 256 + n]);
    *reinterpret_cast<uint4*>(dh + (size_t)n * 128 + kq * 8) = *reinterpret_cast<uint4*>(h);
}

// ---------------- GEMM1 (A split in-kernel, W fp16, 2-term, fused alpha) ------
// block tile 128m x 128n, 8 warps (2x4), warp tile 64x32, k-chunk 16, 2 stages
#define ASTRF 24
#define BSTRH 24
#define A_BYTES (128 * ASTRF * 4)
#define B_BYTES (128 * BSTRH * 2)
#define STAGE_B (A_BYTES + B_BYTES)
#define SMEM_B  (2 * STAGE_B)

__global__ __launch_bounds__(256) void k_gemm1_tc5(
        const float* __restrict__ x,
        const __half* __restrict__ wt,
        const float* __restrict__ a_src, const float* __restrict__ a_dst,
        __half* __restrict__ h1h, float* __restrict__ asrcn, float* __restrict__ adstn,
        int N) {
    extern __shared__ char smc[];
    const int t = threadIdx.x;
    const int warp = t >> 5, lane = t & 31;
    const int wm = warp >> 2, wn = warp & 3;
    const int lm = lane >> 2, lk = lane & 3;
    const int r0 = blockIdx.x * 128;
    const int n0 = blockIdx.y * 128;

    float acc[4][4][4];
#pragma unroll
    for (int i = 0; i < 4; i++)
#pragma unroll
        for (int j = 0; j < 4; j++)
#pragma unroll
            for (int v = 0; v < 4; v++) acc[i][j][v] = 0.f;

    auto issue = [&](int c, int buf) {
        int k0 = c * 16;
        char* base = smc + buf * STAGE_B;
        // A: f32, 128 rows x 16 k = 512 x 16B ops, 2 per thread
#pragma unroll
        for (int i = 0; i < 2; i++) {
            int op = t + i * 256;
            int row = op >> 2, seg = op & 3;
            int gr = r0 + row; if (gr > N - 1) gr = N - 1;
            cpasync16(base + (row * ASTRF + seg * 4) * 4,
                      x + (size_t)gr * 128 + k0 + seg * 4);
        }
        // B: halves, 128 rows x 16 k = 256 x 16B ops, 1 per thread
        {
            int row = t >> 1, seg = t & 1;
            cpasync16(base + A_BYTES + (row * BSTRH + seg * 8) * 2,
                      wt + (size_t)(n0 + row) * 128 + k0 + seg * 8);
        }
        asm volatile("cp.async.commit_group;");
    };

    issue(0, 0);
    for (int c = 0; c < 8; c++) {
        int buf = c & 1;
        if (c < 7) {
            issue(c + 1, buf ^ 1);
            asm volatile("cp.async.wait_group 1;");
        } else {
            asm volatile("cp.async.wait_group 0;");
        }
        __syncthreads();
        const float* As = reinterpret_cast<const float*>(smc + buf * STAGE_B);
        const __half* Bh = reinterpret_cast<const __half*>(smc + buf * STAGE_B + A_BYTES);
        const int kb = lk * 2;

        unsigned Ahf[4][4], Alf[4][4];
#pragma unroll
        for (int mt = 0; mt < 4; mt++) {
            int mrow = wm * 64 + mt * 16 + lm;
            float2 v0 = *reinterpret_cast<const float2*>(As + mrow * ASTRF + kb);
            float2 v1 = *reinterpret_cast<const float2*>(As + (mrow + 8) * ASTRF + kb);
            float2 v2 = *reinterpret_cast<const float2*>(As + mrow * ASTRF + kb + 8);
            float2 v3 = *reinterpret_cast<const float2*>(As + (mrow + 8) * ASTRF + kb + 8);
            fragsplit(v0, Ahf[mt][0], Alf[mt][0]);
            fragsplit(v1, Ahf[mt][1], Alf[mt][1]);
            fragsplit(v2, Ahf[mt][2], Alf[mt][2]);
            fragsplit(v3, Ahf[mt][3], Alf[mt][3]);
        }
        unsigned Bhf[4][2];
#pragma unroll
        for (int nt = 0; nt < 4; nt++) {
            int n = wn * 32 + nt * 8 + lm;
            Bhf[nt][0] = *reinterpret_cast<const unsigned*>(Bh + n * BSTRH + kb);
            Bhf[nt][1] = *reinterpret_cast<const unsigned*>(Bh + n * BSTRH + kb + 8);
        }
#pragma unroll
        for (int mt = 0; mt < 4; mt++)
#pragma unroll
            for (int nt = 0; nt < 4; nt++) {
                mma_f16(acc[mt][nt], Ahf[mt], Bhf[nt]);
                mma_f16(acc[mt][nt], Alf[mt], Bhf[nt]);
            }
        __syncthreads();
    }

    // ---- epilogue: store h1 (fp16) + fused alpha projections ----
    const int h = blockIdx.y * 4 + wn;
    float2 asv[4], adv[4];
#pragma unroll
    for (int nt = 0; nt < 4; nt++) {
        asv[nt] = *reinterpret_cast<const float2*>(a_src + h * 32 + nt * 8 + lk * 2);
        adv[nt] = *reinterpret_cast<const float2*>(a_dst + h * 32 + nt * 8 + lk * 2);
    }
#pragma unroll
    for (int mt = 0; mt < 4; mt++) {
        int row1 = r0 + wm * 64 + mt * 16 + lm;
        int row2 = row1 + 8;
        float s1 = 0.f, d1 = 0.f, s2 = 0.f, d2 = 0.f;
#pragma unroll
        for (int nt = 0; nt < 4; nt++) {
            int col = n0 + wn * 32 + nt * 8 + lk * 2;
            s1 += acc[mt][nt][0] * asv[nt].x + acc[mt][nt][1] * asv[nt].y;
            d1 += acc[mt][nt][0] * adv[nt].x + acc[mt][nt][1] * adv[nt].y;
            s2 += acc[mt][nt][2] * asv[nt].x + acc[mt][nt][3] * asv[nt].y;
            d2 += acc[mt][nt][2] * adv[nt].x + acc[mt][nt][3] * adv[nt].y;
            if (row1 < N)
                *reinterpret_cast<__half2*>(h1h + (size_t)row1 * 256 + col) =
                    __floats2half2_rn(acc[mt][nt][0], acc[mt][nt][1]);
            if (row2 < N)
                *reinterpret_cast<__half2*>(h1h + (size_t)row2 * 256 + col) =
                    __floats2half2_rn(acc[mt][nt][2], acc[mt][nt][3]);
        }
        s1 += __shfl_xor_sync(0xffffffffu, s1, 1); s1 += __shfl_xor_sync(0xffffffffu, s1, 2);
        d1 += __shfl_xor_sync(0xffffffffu, d1, 1); d1 += __shfl_xor_sync(0xffffffffu, d1, 2);
        s2 += __shfl_xor_sync(0xffffffffu, s2, 1); s2 += __shfl_xor_sync(0xffffffffu, s2, 2);
        d2 += __shfl_xor_sync(0xffffffffu, d2, 1); d2 += __shfl_xor_sync(0xffffffffu, d2, 2);
        if (lk == 0) {
            if (row1 < N) { asrcn[row1 * 8 + h] = s1; adstn[row1 * 8 + h] = d1; }
            if (row2 < N) { asrcn[row2 * 8 + h] = s2; adstn[row2 * 8 + h] = d2; }
        }
    }
}

// ----- GAT1 pull aggregation: warp per dst, per-lane head weights, unroll x4 --
__global__ void k_agg1(const int* __restrict__ rowptr, const int* __restrict__ esrc,
                       const float* __restrict__ asrc, const float* __restrict__ adst,
                       const __half* __restrict__ h1h, const float* __restrict__ b1,
                       __half* __restrict__ out1h, int N) {
    int d = (int)(((long long)blockIdx.x * blockDim.x + threadIdx.x) >> 5);
    int lane = threadIdx.x & 31;
    if (d >= N) return;
    int beg = rowptr[d], endp = rowptr[d + 1];
    const int h0 = lane >> 2;
    float ad = adst[d * 8 + h0];
    float den = 0.f;
    float accv[8];
#pragma unroll
    for (int i = 0; i < 8; i++) accv[i] = 0.f;
    for (int base = beg; base < endp; base += 32) {
        int nn = min(32, endp - base);
        int sreg = (base + lane < endp) ? esrc[base + lane] : 0;
        int j = 0;
        for (; j + 3 < nn; j += 4) {
            int s0 = __shfl_sync(0xffffffffu, sreg, j);
            int s1 = __shfl_sync(0xffffffffu, sreg, j + 1);
            int s2 = __shfl_sync(0xffffffffu, sreg, j + 2);
            int s3 = __shfl_sync(0xffffffffu, sreg, j + 3);
            float w0 = __expf(lrelu(asrc[s0 * 8 + h0] + ad));
            float w1 = __expf(lrelu(asrc[s1 * 8 + h0] + ad));
            float w2 = __expf(lrelu(asrc[s2 * 8 + h0] + ad));
            float w3 = __expf(lrelu(asrc[s3 * 8 + h0] + ad));
            den += (w0 + w1) + (w2 + w3);
            uint4 r0 = *reinterpret_cast<const uint4*>(h1h + (size_t)s0 * 256 + lane * 8);
            uint4 r1 = *reinterpret_cast<const uint4*>(h1h + (size_t)s1 * 256 + lane * 8);
            uint4 r2 = *reinterpret_cast<const uint4*>(h1h + (size_t)s2 * 256 + lane * 8);
            uint4 r3 = *reinterpret_cast<const uint4*>(h1h + (size_t)s3 * 256 + lane * 8);
            {
                float2 f0 = __half22float2(*reinterpret_cast<__half2*>(&r0.x));
                float2 f1 = __half22float2(*reinterpret_cast<__half2*>(&r0.y));
                float2 f2 = __half22float2(*reinterpret_cast<__half2*>(&r0.z));
                float2 f3 = __half22float2(*reinterpret_cast<__half2*>(&r0.w));
                accv[0] += f0.x * w0; accv[1] += f0.y * w0;
                accv[2] += f1.x * w0; accv[3] += f1.y * w0;
                accv[4] += f2.x * w0; accv[5] += f2.y * w0;
                accv[6] += f3.x * w0; accv[7] += f3.y * w0;
            }
            {
                float2 f0 = __half22float2(*reinterpret_cast<__half2*>(&r1.x));
                float2 f1 = __half22float2(*reinterpret_cast<__half2*>(&r1.y));
                float2 f2 = __half22float2(*reinterpret_cast<__half2*>(&r1.z));
                float2 f3 = __half22float2(*reinterpret_cast<__half2*>(&r1.w));
                accv[0] += f0.x * w1; accv[1] += f0.y * w1;
                accv[2] += f1.x * w1; accv[3] += f1.y * w1;
                accv[4] += f2.x * w1; accv[5] += f2.y * w1;
                accv[6] += f3.x * w1; accv[7] += f3.y * w1;
            }
            {
                float2 f0 = __half22float2(*reinterpret_cast<__half2*>(&r2.x));
                float2 f1 = __half22float2(*reinterpret_cast<__half2*>(&r2.y));
                float2 f2 = __half22float2(*reinterpret_cast<__half2*>(&r2.z));
                float2 f3 = __half22float2(*reinterpret_cast<__half2*>(&r2.w));
                accv[0] += f0.x * w2; accv[1] += f0.y * w2;
                accv[2] += f1.x * w2; accv[3] += f1.y * w2;
                accv[4] += f2.x * w2; accv[5] += f2.y * w2;
                accv[6] += f3.x * w2; accv[7] += f3.y * w2;
            }
            {
                float2 f0 = __half22float2(*reinterpret_cast<__half2*>(&r3.x));
                float2 f1 = __half22float2(*reinterpret_cast<__half2*>(&r3.y));
                float2 f2 = __half22float2(*reinterpret_cast<__half2*>(&r3.z));
                float2 f3 = __half22float2(*reinterpret_cast<__half2*>(&r3.w));
                accv[0] += f0.x * w3; accv[1] += f0.y * w3;
                accv[2] += f1.x * w3; accv[3] += f1.y * w3;
                accv[4] += f2.x * w3; accv[5] += f2.y * w3;
                accv[6] += f3.x * w3; accv[7] += f3.y * w3;
            }
        }
        for (; j < nn; j++) {
            int s = __shfl_sync(0xffffffffu, sreg, j);
            float a = __expf(lrelu(asrc[s * 8 + h0] + ad));
            den += a;
            uint4 r = *reinterpret_cast<const uint4*>(h1h + (size_t)s * 256 + lane * 8);
            float2 f0 = __half22float2(*reinterpret_cast<__half2*>(&r.x));
            float2 f1 = __half22float2(*reinterpret_cast<__half2*>(&r.y));
            float2 f2 = __half22float2(*reinterpret_cast<__half2*>(&r.z));
            float2 f3 = __half22float2(*reinterpret_cast<__half2*>(&r.w));
            accv[0] += f0.x * a; accv[1] += f0.y * a;
            accv[2] += f1.x * a; accv[3] += f1.y * a;
            accv[4] += f2.x * a; accv[5] += f2.y * a;
            accv[6] += f3.x * a; accv[7] += f3.y * a;
        }
    }
    float rs = 1.f / den;
    const float4* bp = reinterpret_cast<const float4*>(b1 + lane * 8);
    float4 bb0 = bp[0], bb1 = bp[1];
    float o[8];
    o[0] = eluf(accv[0] * rs + bb0.x); o[1] = eluf(accv[1] * rs + bb0.y);
    o[2] = eluf(accv[2] * rs + bb0.z); o[3] = eluf(accv[3] * rs + bb0.w);
    o[4] = eluf(accv[4] * rs + bb1.x); o[5] = eluf(accv[5] * rs + bb1.y);
    o[6] = eluf(accv[6] * rs + bb1.z); o[7] = eluf(accv[7] * rs + bb1.w);
    __half2 p0 = __floats2half2_rn(o[0], o[1]);
    __half2 p1 = __floats2half2_rn(o[2], o[3]);
    __half2 p2 = __floats2half2_rn(o[4], o[5]);
    __half2 p3 = __floats2half2_rn(o[6], o[7]);
    uint4 pk;
    pk.x = *reinterpret_cast<unsigned*>(&p0);
    pk.y = *reinterpret_cast<unsigned*>(&p1);
    pk.z = *reinterpret_cast<unsigned*>(&p2);
    pk.w = *reinterpret_cast<unsigned*>(&p3);
    *reinterpret_cast<uint4*>(out1h + (size_t)d * 256 + lane * 8) = pk;
}

// ----- GEMM2: h2 = x2[N,256] @ W2[256,16], fp16 in (uint4), fused alpha2 -----
__global__ void k_gemm2(const __half* __restrict__ x2h, const float* __restrict__ W2,
                        const float* __restrict__ a_src2, const float* __restrict__ a_dst2,
                        __half* __restrict__ h2h, float* __restrict__ asrc2n,
                        float* __restrict__ adst2n, int N) {
    __shared__ float Wsh[256 * 16];
    int t = threadIdx.x;
    for (int i = t; i < 4096; i += 256) Wsh[i] = W2[i];
    __syncthreads();
    int n = blockIdx.x * 16 + (t >> 4);
    int c = t & 15;
    if (n >= N) return;
    float acc = 0.f;
    const uint4* xr4 = reinterpret_cast<const uint4*>(x2h + (size_t)n * 256);
#pragma unroll 8
    for (int kq = 0; kq < 32; kq++) {
        uint4 r = xr4[kq];
        float2 f0 = __half22float2(*reinterpret_cast<__half2*>(&r.x));
        float2 f1 = __half22float2(*reinterpret_cast<__half2*>(&r.y));
        float2 f2 = __half22float2(*reinterpret_cast<__half2*>(&r.z));
        float2 f3 = __half22float2(*reinterpret_cast<__half2*>(&r.w));
        const float* wb = Wsh + (kq * 8) * 16 + c;
        acc += f0.x * wb[0]   + f0.y * wb[16]
             + f1.x * wb[32]  + f1.y * wb[48]
             + f2.x * wb[64]  + f2.y * wb[80]
             + f3.x * wb[96]  + f3.y * wb[112];
    }
    h2h[(size_t)n * 16 + c] = __float2half(acc);
    float r1 = acc * a_src2[c];
    float r2 = acc * a_dst2[c];
#pragma unroll
    for (int m = 8; m >= 1; m >>= 1) {
        r1 += __shfl_xor_sync(0xffffffffu, r1, m, 16);
        r2 += __shfl_xor_sync(0xffffffffu, r2, m, 16);
    }
    if (c == 0) { asrc2n[n] = r1; adst2n[n] = r2; }
}

// ----- GAT2 pull aggregation + fused GCN transform (h3), unroll x4 -----------
__global__ void k_agg2(const int* __restrict__ rowptr, const int* __restrict__ esrc,
                       const float* __restrict__ asrc, const float* __restrict__ adst,
                       const __half* __restrict__ h2h, const float* __restrict__ b2,
                       const float* __restrict__ W3, __half* __restrict__ gh, int N) {
    __shared__ float W3s[256];
    if (threadIdx.x < 256) W3s[threadIdx.x] = W3[threadIdx.x];
    __syncthreads();
    long long gt = (long long)blockIdx.x * blockDim.x + threadIdx.x;
    int d = (int)(gt >> 2);
    int q = threadIdx.x & 3;
    if (d >= N) return;
    int beg = rowptr[d], endp = rowptr[d + 1];
    float ad = adst[d];
    float den = 0.f;
    float4 acc = {0, 0, 0, 0};
    int idx = beg;
    for (; idx + 3 < endp; idx += 4) {
        int s0 = esrc[idx], s1 = esrc[idx + 1], s2 = esrc[idx + 2], s3 = esrc[idx + 3];
        float w0 = __expf(lrelu(asrc[s0] + ad));
        float w1 = __expf(lrelu(asrc[s1] + ad));
        float w2 = __expf(lrelu(asrc[s2] + ad));
        float w3 = __expf(lrelu(asrc[s3] + ad));
        den += (w0 + w1) + (w2 + w3);
        uint2 r0 = *reinterpret_cast<const uint2*>(h2h + (size_t)s0 * 16 + q * 4);
        uint2 r1 = *reinterpret_cast<const uint2*>(h2h + (size_t)s1 * 16 + q * 4);
        uint2 r2 = *reinterpret_cast<const uint2*>(h2h + (size_t)s2 * 16 + q * 4);
        uint2 r3 = *reinterpret_cast<const uint2*>(h2h + (size_t)s3 * 16 + q * 4);
        float2 a0 = __half22float2(*reinterpret_cast<__half2*>(&r0.x));
        float2 a1 = __half22float2(*reinterpret_cast<__half2*>(&r0.y));
        float2 b0 = __half22float2(*reinterpret_cast<__half2*>(&r1.x));
        float2 b1v = __half22float2(*reinterpret_cast<__half2*>(&r1.y));
        float2 c0 = __half22float2(*reinterpret_cast<__half2*>(&r2.x));
        float2 c1 = __half22float2(*reinterpret_cast<__half2*>(&r2.y));
        float2 e0 = __half22float2(*reinterpret_cast<__half2*>(&r3.x));
        float2 e1 = __half22float2(*reinterpret_cast<__half2*>(&r3.y));
        acc.x += (a0.x * w0 + b0.x * w1) + (c0.x * w2 + e0.x * w3);
        acc.y += (a0.y * w0 + b0.y * w1) + (c0.y * w2 + e0.y * w3);
        acc.z += (a1.x * w0 + b1v.x * w1) + (c1.x * w2 + e1.x * w3);
        acc.w += (a1.y * w0 + b1v.y * w1) + (c1.y * w2 + e1.y * w3);
    }
    for (; idx < endp; idx++) {
        int s = esrc[idx];
        float wgt = __expf(lrelu(asrc[s] + ad));
        den += wgt;
        uint2 r = *reinterpret_cast<const uint2*>(h2h + (size_t)s * 16 + q * 4);
        float2 f0 = __half22float2(*reinterpret_cast<__half2*>(&r.x));
        float2 f1 = __half22float2(*reinterpret_cast<__half2*>(&r.y));
        acc.x += f0.x * wgt; acc.y += f0.y * wgt;
        acc.z += f1.x * wgt; acc.w += f1.y * wgt;
    }
    float rr = 1.f / den;
    float4 bb = reinterpret_cast<const float4*>(b2)[q];
    float4 o;
    o.x = eluf(acc.x * rr + bb.x); o.y = eluf(acc.y * rr + bb.y);
    o.z = eluf(acc.z * rr + bb.z); o.w = eluf(acc.w * rr + bb.w);

    float v[16];
#pragma unroll
    for (int r = 0; r < 4; r++) {
        v[r * 4 + 0] = __shfl_sync(0xffffffffu, o.x, r, 4);
        v[r * 4 + 1] = __shfl_sync(0xffffffffu, o.y, r, 4);
        v[r * 4 + 2] = __shfl_sync(0xffffffffu, o.z, r, 4);
        v[r * 4 + 3] = __shfl_sync(0xffffffffu, o.w, r, 4);
    }
    float dv = rsqrtf((float)(endp - beg));
    float gacc[4];
#pragma unroll
    for (int j = 0; j < 4; j++) {
        int cc = q * 4 + j;
        float a = 0.f;
#pragma unroll
        for (int k = 0; k < 16; k++) a += v[k] * W3s[k * 16 + cc];
        gacc[j] = a * dv;
    }
    __half2 p0 = __floats2half2_rn(gacc[0], gacc[1]);
    __half2 p1 = __floats2half2_rn(gacc[2], gacc[3]);
    uint2 pk;
    pk.x = *reinterpret_cast<unsigned*>(&p0);
    pk.y = *reinterpret_cast<unsigned*>(&p1);
    *reinterpret_cast<uint2*>(gh + (size_t)d * 16 + q * 4) = pk;
}

// ----- GCN pull aggregation + finalize (fp16 gather), unroll x4 ---------------
__global__ void k_agg3(const int* __restrict__ rowptr, const int* __restrict__ esrc,
                       const __half* __restrict__ gh, const float* __restrict__ b3,
                       float* __restrict__ out, int N) {
    long long gt = (long long)blockIdx.x * blockDim.x + threadIdx.x;
    int d = (int)(gt >> 2);
    int q = threadIdx.x & 3;
    if (d >= N) return;
    int beg = rowptr[d], endp = rowptr[d + 1];
    float4 acc = {0, 0, 0, 0};
    int idx = beg;
    for (; idx + 3 < endp; idx += 4) {
        int s0 = esrc[idx], s1 = esrc[idx + 1], s2 = esrc[idx + 2], s3 = esrc[idx + 3];
        uint2 r0 = *reinterpret_cast<const uint2*>(gh + (size_t)s0 * 16 + q * 4);
        uint2 r1 = *reinterpret_cast<const uint2*>(gh + (size_t)s1 * 16 + q * 4);
        uint2 r2 = *reinterpret_cast<const uint2*>(gh + (size_t)s2 * 16 + q * 4);
        uint2 r3 = *reinterpret_cast<const uint2*>(gh + (size_t)s3 * 16 + q * 4);
        float2 a0 = __half22float2(*reinterpret_cast<__half2*>(&r0.x));
        float2 a1 = __half22float2(*reinterpret_cast<__half2*>(&r0.y));
        float2 b0 = __half22float2(*reinterpret_cast<__half2*>(&r1.x));
        float2 b1v = __half22float2(*reinterpret_cast<__half2*>(&r1.y));
        float2 c0 = __half22float2(*reinterpret_cast<__half2*>(&r2.x));
        float2 c1 = __half22float2(*reinterpret_cast<__half2*>(&r2.y));
        float2 e0 = __half22float2(*reinterpret_cast<__half2*>(&r3.x));
        float2 e1 = __half22float2(*reinterpret_cast<__half2*>(&r3.y));
        acc.x += (a0.x + b0.x) + (c0.x + e0.x);
        acc.y += (a0.y + b0.y) + (c0.y + e0.y);
        acc.z += (a1.x + b1v.x) + (c1.x + e1.x);
        acc.w += (a1.y + b1v.y) + (c1.y + e1.y);
    }
    for (; idx < endp; idx++) {
        int s = esrc[idx];
        uint2 r = *reinterpret_cast<const uint2*>(gh + (size_t)s * 16 + q * 4);
        float2 f0 = __half22float2(*reinterpret_cast<__half2*>(&r.x));
        float2 f1 = __half22float2(*reinterpret_cast<__half2*>(&r.y));
        acc.x += f0.x; acc.y += f0.y; acc.z += f1.x; acc.w += f1.y;
    }
    float dv = rsqrtf((float)(endp - beg));
    float4 bb = reinterpret_cast<const float4*>(b3)[q];
    float4 o;
    o.x = acc.x * dv + bb.x; o.y = acc.y * dv + bb.y;
    o.z = acc.z * dv + bb.z; o.w = acc.w * dv + bb.w;
    reinterpret_cast<float4*>(out + (size_t)d * 16)[q] = o;
}

// ---------------------------------------------------------------------------
extern "C" void kernel_launch(void* const* d_in, const int* in_sizes, int n_in,
                              void* d_out, int out_size) {
    const float* x      = (const float*)d_in[0];
    const int*   ei     = (const int*)d_in[1];
    const float* W1     = (const float*)d_in[2];
    const float* a_src1 = (const float*)d_in[3];
    const float* a_dst1 = (const float*)d_in[4];
    const float* b1     = (const float*)d_in[5];
    const float* W2     = (const float*)d_in[6];
    const float* a_src2 = (const float*)d_in[7];
    const float* a_dst2 = (const float*)d_in[8];
    const float* b2     = (const float*)d_in[9];
    const float* W3     = (const float*)d_in[10];
    const float* b3     = (const float*)d_in[11];
    float* out = (float*)d_out;

    const int N = in_sizes[0] / 128;
    const int E = in_sizes[1] / 2;
    const int ET = E + N;

    float *asrc1, *adst1, *asrc2, *adst2;
    __half *h1h, *out1h, *h2h, *gh, *wt;
    int *degi, *cursor, *rowptr, *esrc;
    void* p;
    cudaGetSymbolAddress(&p, g_h1h);    h1h    = (__half*)p;
    cudaGetSymbolAddress(&p, g_asrc1);  asrc1  = (float*)p;
    cudaGetSymbolAddress(&p, g_adst1);  adst1  = (float*)p;
    cudaGetSymbolAddress(&p, g_out1h);  out1h  = (__half*)p;
    cudaGetSymbolAddress(&p, g_h2h);    h2h    = (__half*)p;
    cudaGetSymbolAddress(&p, g_asrc2);  asrc2  = (float*)p;
    cudaGetSymbolAddress(&p, g_adst2);  adst2  = (float*)p;
    cudaGetSymbolAddress(&p, g_gh);     gh     = (__half*)p;
    cudaGetSymbolAddress(&p, g_degi);   degi   = (int*)p;
    cudaGetSymbolAddress(&p, g_cursor); cursor = (int*)p;
    cudaGetSymbolAddress(&p, g_rowptr); rowptr = (int*)p;
    cudaGetSymbolAddress(&p, g_esrc);   esrc   = (int*)p;
    cudaGetSymbolAddress(&p, g_wt);     wt     = (__half*)p;

    static cudaStream_t s2 = nullptr;
    static cudaEvent_t evFork = nullptr, evJoin = nullptr, evW = nullptr;
    static int smem_set = 0;
    if (!s2) {
        cudaStreamCreateWithFlags(&s2, cudaStreamNonBlocking);
        cudaEventCreateWithFlags(&evFork, cudaEventDisableTiming);
        cudaEventCreateWithFlags(&evJoin, cudaEventDisableTiming);
        cudaEventCreateWithFlags(&evW, cudaEventDisableTiming);
    }
    if (!smem_set) {
        cudaFuncSetAttribute(k_gemm1_tc5,
                             cudaFuncAttributeMaxDynamicSharedMemorySize, SMEM_B);
        smem_set = 1;
    }

    const int B = 256;

    // ---- fork: W1 convert + CSR chain on s2 ----
    cudaEventRecord(evFork, 0);
    cudaStreamWaitEvent(s2, evFork, 0);

    k_splitW<<<(256 * 16 + B - 1) / B, B, 0, s2>>>(W1, wt);
    cudaEventRecord(evW, s2);
    cudaMemsetAsync(degi, 0, (size_t)N * sizeof(int), s2);
    k_deg<<<(ET + B - 1) / B, B, 0, s2>>>(ei, E, N, degi);
    k_scan<<<1, 1024, 0, s2>>>(degi, rowptr, cursor, N, ET);
    {
        int threads = (ET + 1) / 2;
        k_fill<<<(threads + B - 1) / B, B, 0, s2>>>(ei, E, N, cursor, esrc);
    }
    cudaEventRecord(evJoin, s2);

    // main stream: tensor-core GEMM1 reads x (f32) directly; needs wt
    cudaStreamWaitEvent(0, evW, 0);
    {
        dim3 grid((N + 127) / 128, 2);
        k_gemm1_tc5<<<grid, 256, SMEM_B>>>(
            x, wt, a_src1, a_dst1, h1h, asrc1, adst1, N);
    }

    // ---- join: agg1 needs CSR ----
    cudaStreamWaitEvent(0, evJoin, 0);

    {
        long long tot = (long long)N * 32;   // warp per dst
        k_agg1<<<(unsigned)((tot + B - 1) / B), B>>>(rowptr, esrc, asrc1, adst1, h1h, b1, out1h, N);
    }

    // Layer 2: GAT(256 -> 16, 1 head)
    k_gemm2<<<(N + 15) / 16, B>>>(out1h, W2, a_src2, a_dst2, h2h, asrc2, adst2, N);
    {
        long long tot = (long long)N * 4;
        k_agg2<<<(unsigned)((tot + B - 1) / B), B>>>(rowptr, esrc, asrc2, adst2, h2h, b2, W3, gh, N);
    }

    // Layer 3: GCN aggregation + finalize
    {
        long long tot = (long long)N * 4;
        k_agg3<<<(unsigned)((tot + B - 1) / B), B>>>(rowptr, esrc, gh, b3, out, N);
    }
}